// round 5
// baseline (speedup 1.0000x reference)
#include <cuda_runtime.h>
#include <cstdint>

// ---------------- problem constants ----------------
#define HID   4096
#define NEXP  4
#define RNK   8
#define MAXN  16384

// ---------------- GEMM tiling ----------------
#define BM 128
#define BN 128
#define BK 32
#define NCHUNK (HID / BK)            // 128
#define ROWB   144                    // 32 floats + 4 pad = 144 bytes/row
#define A_STAGE (BM * ROWB)           // 18432
#define STAGE_BYTES (2 * A_STAGE)     // 36864 (A then B)
#define STAGES 3
#define DYN_SMEM (STAGES * STAGE_BYTES)   // 110592

// scratch (allocation-free rule: __device__ globals live in bss)
__device__ float g_zs[MAXN * RNK];
__device__ int   g_top1[MAXN];
__device__ float g_xtf[(size_t)MAXN * HID];   // tf32-rounded x   (256 MB)
__device__ float g_wtf[(size_t)HID * HID];    // tf32-rounded W   (64 MB)

// ---------------- PTX helpers ----------------
__device__ __forceinline__ uint32_t smem_u32(const void* p) {
    uint32_t a;
    asm("{ .reg .u64 t; cvta.to.shared.u64 t, %1; cvt.u32.u64 %0, t; }"
        : "=r"(a) : "l"(p));
    return a;
}
__device__ __forceinline__ void cp_async16(uint32_t dst, const void* src) {
    asm volatile("cp.async.cg.shared.global [%0], [%1], 16;"
                 :: "r"(dst), "l"(src) : "memory");
}
#define CP_COMMIT() asm volatile("cp.async.commit_group;" ::: "memory")
#define CP_WAIT2()  asm volatile("cp.async.wait_group 2;"  ::: "memory")

__device__ __forceinline__ void ldsm4(uint32_t* d, uint32_t addr) {
    asm volatile("ldmatrix.sync.aligned.m8n8.x4.shared.b16 {%0,%1,%2,%3}, [%4];"
                 : "=r"(d[0]), "=r"(d[1]), "=r"(d[2]), "=r"(d[3]) : "r"(addr));
}
__device__ __forceinline__ float f2tf_f(float x) {
    uint32_t y;
    asm("cvt.rna.tf32.f32 %0, %1;" : "=r"(y) : "r"(__float_as_uint(x)));
    return __uint_as_float(y);
}
__device__ __forceinline__ void mma_tf32(float* c, const uint32_t* a,
                                         uint32_t b0, uint32_t b1) {
    asm volatile(
        "mma.sync.aligned.m16n8k8.row.col.f32.tf32.tf32.f32 "
        "{%0,%1,%2,%3},{%4,%5,%6,%7},{%8,%9},{%0,%1,%2,%3};"
        : "+f"(c[0]), "+f"(c[1]), "+f"(c[2]), "+f"(c[3])
        : "r"(a[0]), "r"(a[1]), "r"(a[2]), "r"(a[3]), "r"(b0), "r"(b1));
}

// ---------------------------------------------------------------------------
// Kernel P: one-shot tf32 rounding pre-pass (src -> dst), grid-stride float4
// ---------------------------------------------------------------------------
__global__ void cvt_tf32_kernel(const float4* __restrict__ src,
                                float4* __restrict__ dst, int n4) {
    for (int i = blockIdx.x * blockDim.x + threadIdx.x; i < n4;
         i += gridDim.x * blockDim.x) {
        float4 v = src[i];
        v.x = f2tf_f(v.x); v.y = f2tf_f(v.y);
        v.z = f2tf_f(v.z); v.w = f2tf_f(v.w);
        dst[i] = v;
    }
}

// ---------------------------------------------------------------------------
// Kernel A: per-token gating + LoRA z = A_e . x
// ---------------------------------------------------------------------------
__global__ void gate_z_kernel(const float* __restrict__ x,
                              const float* __restrict__ gw,
                              const float* __restrict__ bias,
                              const float* __restrict__ lA) {
    const int n    = blockIdx.x;
    const int tid  = threadIdx.x;
    const int wid  = tid >> 5;
    const int lane = tid & 31;

    const float4* xr = reinterpret_cast<const float4*>(x + (size_t)n * HID);
    __shared__ float sred[4][RNK];
    __shared__ int   s_e;

    float a[NEXP] = {0.f, 0.f, 0.f, 0.f};
    const float4* gw4 = reinterpret_cast<const float4*>(gw);
    for (int h = tid; h < HID / 4; h += 128) {
        float4 xv = xr[h];
#pragma unroll
        for (int e = 0; e < NEXP; e++) {
            float4 g = gw4[e * (HID / 4) + h];
            a[e] += xv.x * g.x + xv.y * g.y + xv.z * g.z + xv.w * g.w;
        }
    }
#pragma unroll
    for (int e = 0; e < NEXP; e++)
#pragma unroll
        for (int off = 16; off > 0; off >>= 1)
            a[e] += __shfl_xor_sync(0xffffffffu, a[e], off);
    if (lane == 0)
#pragma unroll
        for (int e = 0; e < NEXP; e++) sred[wid][e] = a[e];
    __syncthreads();
    if (tid == 0) {
        float best = -3.4e38f; int be = 0;
#pragma unroll
        for (int e = 0; e < NEXP; e++) {
            float v = sred[0][e] + sred[1][e] + sred[2][e] + sred[3][e] + bias[e];
            if (v > best) { best = v; be = e; }
        }
        s_e = be;
        g_top1[n] = be;
    }
    __syncthreads();

    const int e = s_e;
    const float4* A4 = reinterpret_cast<const float4*>(lA + (size_t)e * RNK * HID);
    float z[RNK];
#pragma unroll
    for (int r = 0; r < RNK; r++) z[r] = 0.f;
    for (int h = tid; h < HID / 4; h += 128) {
        float4 xv = xr[h];
#pragma unroll
        for (int r = 0; r < RNK; r++) {
            float4 g = A4[r * (HID / 4) + h];
            z[r] += xv.x * g.x + xv.y * g.y + xv.z * g.z + xv.w * g.w;
        }
    }
#pragma unroll
    for (int r = 0; r < RNK; r++)
#pragma unroll
        for (int off = 16; off > 0; off >>= 1)
            z[r] += __shfl_xor_sync(0xffffffffu, z[r], off);
    __syncthreads();
    if (lane == 0)
#pragma unroll
        for (int r = 0; r < RNK; r++) sred[wid][r] = z[r];
    __syncthreads();
    if (tid < RNK)
        g_zs[(size_t)n * RNK + tid] =
            sred[0][tid] + sred[1][tid] + sred[2][tid] + sred[3][tid];
}

// ---------------------------------------------------------------------------
// Kernel B: tf32 mma.sync GEMM (pre-rounded operands) + fused LoRA epilogue
// 256 threads, CTA tile 128x128x32, warp tile 64x32, 3-stage cp.async.
// ---------------------------------------------------------------------------
__device__ __forceinline__ void load_chunk(uint32_t base,
                                           const float* __restrict__ x,
                                           const float* __restrict__ w,
                                           int m0, int n0, int k0, int tid) {
    const int seg = tid & 7;       // 16B segment in 128B row
    const int r0  = tid >> 3;      // 0..31
    const float* ga = x + (size_t)(m0 + r0) * HID + k0 + seg * 4;
    const float* gb = w + (size_t)(n0 + r0) * HID + k0 + seg * 4;
#pragma unroll
    for (int i = 0; i < 4; i++) {
        const uint32_t off = (uint32_t)(r0 + i * 32) * ROWB + seg * 16;
        cp_async16(base + off,           ga + (size_t)i * 32 * HID);
        cp_async16(base + A_STAGE + off, gb + (size_t)i * 32 * HID);
    }
}

__global__ __launch_bounds__(256)
void mma_gemm_kernel(const float* __restrict__ x,
                     const float* __restrict__ w,
                     const float* __restrict__ lB,
                     float* __restrict__ out) {
    extern __shared__ __align__(16) char dsm[];
    const uint32_t tiles = smem_u32(dsm);

    const int tid  = threadIdx.x;
    const int wid  = tid >> 5;
    const int lane = tid & 31;
    const int wm   = (wid & 1) * 64;     // warp m offset in CTA tile
    const int wn   = (wid >> 1) * 32;    // warp n offset
    const int m0   = blockIdx.y * BM;
    const int n0   = blockIdx.x * BN;

    // ldmatrix per-lane address offsets
    const int q = lane >> 3, r = lane & 7;
    uint32_t aoff[4], boff[4];
#pragma unroll
    for (int mt = 0; mt < 4; mt++)
        aoff[mt] = (uint32_t)(wm + mt * 16 + (q & 1) * 8 + r) * ROWB + (q >> 1) * 16;
#pragma unroll
    for (int nt = 0; nt < 4; nt++)
        boff[nt] = (uint32_t)(wn + nt * 8 + r) * ROWB + q * 16;

    float c[4][4][4];
#pragma unroll
    for (int i = 0; i < 4; i++)
#pragma unroll
        for (int j = 0; j < 4; j++)
#pragma unroll
            for (int t = 0; t < 4; t++) c[i][j][t] = 0.f;

    // prologue: stages 0, 1
    load_chunk(tiles + 0 * STAGE_BYTES, x, w, m0, n0, 0 * BK, tid);
    CP_COMMIT();
    load_chunk(tiles + 1 * STAGE_BYTES, x, w, m0, n0, 1 * BK, tid);
    CP_COMMIT();

    for (int k = 0; k < NCHUNK; k++) {
        if (k + 2 < NCHUNK)
            load_chunk(tiles + ((k + 2) % STAGES) * STAGE_BYTES,
                       x, w, m0, n0, (k + 2) * BK, tid);
        CP_COMMIT();           // empty groups at tail keep wait positional
        CP_WAIT2();            // chunk k resident
        __syncthreads();

        const uint32_t sA = tiles + (k % STAGES) * STAGE_BYTES;
        const uint32_t sB = sA + A_STAGE;

#pragma unroll
        for (int j = 0; j < 2; j++) {            // k-step pairs
            uint32_t Bf[4][4];
#pragma unroll
            for (int nt = 0; nt < 4; nt++)
                ldsm4(Bf[nt], sB + boff[nt] + j * 64);
#pragma unroll
            for (int half = 0; half < 2; half++) {
                uint32_t Af[4][4];
#pragma unroll
                for (int mt = 0; mt < 4; mt++)
                    ldsm4(Af[mt], sA + aoff[mt] + (2 * j + half) * 32);
#pragma unroll
                for (int mt = 0; mt < 4; mt++)
#pragma unroll
                    for (int nt = 0; nt < 4; nt++)
                        mma_tf32(c[mt][nt], Af[mt],
                                 Bf[nt][2 * half], Bf[nt][2 * half + 1]);
            }
        }
        __syncthreads();       // stage k%3 is refilled next iteration
    }

    // ---- epilogue: add LoRA delta, write out ----
    const int rowg = lane >> 2;          // 0..7
    const int colg = (lane & 3) * 2;
#pragma unroll
    for (int mt = 0; mt < 4; mt++) {
#pragma unroll
        for (int hr = 0; hr < 2; hr++) {
            const int row = m0 + wm + mt * 16 + hr * 8 + rowg;
            const int e   = g_top1[row];
            const float4* zz = reinterpret_cast<const float4*>(g_zs + (size_t)row * RNK);
            const float4 z0 = zz[0], z1 = zz[1];
            const float* lbe = lB + (size_t)e * HID * RNK;
            float* orow = out + (size_t)row * HID;
#pragma unroll
            for (int nt = 0; nt < 4; nt++) {
                const int col = n0 + wn + nt * 8 + colg;
                const float4* bp =
                    reinterpret_cast<const float4*>(lbe + (size_t)col * RNK);
                const float4 b0 = bp[0], b1 = bp[1];
                const float4* bq =
                    reinterpret_cast<const float4*>(lbe + (size_t)(col + 1) * RNK);
                const float4 q0 = bq[0], q1 = bq[1];
                float d0 = z0.x * b0.x + z0.y * b0.y + z0.z * b0.z + z0.w * b0.w
                         + z1.x * b1.x + z1.y * b1.y + z1.z * b1.z + z1.w * b1.w;
                float d1 = z0.x * q0.x + z0.y * q0.y + z0.z * q0.z + z0.w * q0.w
                         + z1.x * q1.x + z1.y * q1.y + z1.z * q1.z + z1.w * q1.w;
                float2 res = make_float2(c[mt][nt][hr * 2 + 0] + d0,
                                         c[mt][nt][hr * 2 + 1] + d1);
                *reinterpret_cast<float2*>(orow + col) = res;
            }
        }
    }
}

// ---------------------------------------------------------------------------
extern "C" void kernel_launch(void* const* d_in, const int* in_sizes, int n_in,
                              void* d_out, int out_size) {
    const float* x    = (const float*)d_in[0];
    const float* W_up = (const float*)d_in[1];
    const float* gw   = (const float*)d_in[2];
    const float* bias = (const float*)d_in[3];
    const float* lA   = (const float*)d_in[4];
    const float* lBm  = (const float*)d_in[5];
    float* out        = (float*)d_out;

    const int N = in_sizes[0] / HID;   // 16384 tokens

    cudaFuncSetAttribute(mma_gemm_kernel,
                         cudaFuncAttributeMaxDynamicSharedMemorySize, DYN_SMEM);

    // device-symbol addresses (host-side; cheap, graph-capturable)
    float* xtf = nullptr;
    float* wtf = nullptr;
    cudaGetSymbolAddress((void**)&xtf, g_xtf);
    cudaGetSymbolAddress((void**)&wtf, g_wtf);

    // pre-pass: tf32-round x and W once
    const int n4x = N * HID / 4;
    const int n4w = HID * HID / 4;
    cvt_tf32_kernel<<<2048, 256>>>((const float4*)x,    (float4*)xtf, n4x);
    cvt_tf32_kernel<<<2048, 256>>>((const float4*)W_up, (float4*)wtf, n4w);

    gate_z_kernel<<<N, 128>>>(x, gw, bias, lA);

    dim3 grid(HID / BN, N / BM);       // (32, 128)
    mma_gemm_kernel<<<grid, 256, DYN_SMEM>>>(xtf, wtf, lBm, out);
}

// round 6
// speedup vs baseline: 1.2333x; 1.2333x over previous
#include <cuda_runtime.h>
#include <cstdint>

// ---------------- problem constants ----------------
#define HID   4096
#define NEXP  4
#define RNK   8
#define MAXN  16384

// ---------------- GEMM tiling ----------------
#define BM 128
#define BN 128
#define BK 32
#define NCHUNK (HID / BK)            // 128
#define ROWB   144                    // 32 floats + 4 pad = 144 bytes/row
#define A_STAGE (BM * ROWB)           // 18432
#define STAGE_BYTES (2 * A_STAGE)     // 36864 (A then B)
#define STAGES 3
#define DYN_SMEM (STAGES * STAGE_BYTES)   // 110592

// scratch (allocation-free rule: __device__ globals live in bss)
__device__ float g_zs[MAXN * RNK];
__device__ int   g_top1[MAXN];
__device__ float g_xtf[(size_t)MAXN * HID];   // tf32-rounded x   (256 MB)
__device__ float g_wtf[(size_t)HID * HID];    // tf32-rounded W   (64 MB)

// ---------------- PTX helpers ----------------
__device__ __forceinline__ uint32_t smem_u32(const void* p) {
    uint32_t a;
    asm("{ .reg .u64 t; cvta.to.shared.u64 t, %1; cvt.u32.u64 %0, t; }"
        : "=r"(a) : "l"(p));
    return a;
}
__device__ __forceinline__ void cp_async16(uint32_t dst, const void* src) {
    asm volatile("cp.async.cg.shared.global [%0], [%1], 16;"
                 :: "r"(dst), "l"(src) : "memory");
}
#define CP_COMMIT() asm volatile("cp.async.commit_group;" ::: "memory")
#define CP_WAIT2()  asm volatile("cp.async.wait_group 2;"  ::: "memory")

__device__ __forceinline__ void ldsm4(uint32_t* d, uint32_t addr) {
    asm volatile("ldmatrix.sync.aligned.m8n8.x4.shared.b16 {%0,%1,%2,%3}, [%4];"
                 : "=r"(d[0]), "=r"(d[1]), "=r"(d[2]), "=r"(d[3]) : "r"(addr));
}
__device__ __forceinline__ float f2tf_f(float x) {
    uint32_t y;
    asm("cvt.rna.tf32.f32 %0, %1;" : "=r"(y) : "r"(__float_as_uint(x)));
    return __uint_as_float(y);
}
__device__ __forceinline__ void mma_tf32(float* c, const uint32_t* a,
                                         uint32_t b0, uint32_t b1) {
    asm volatile(
        "mma.sync.aligned.m16n8k8.row.col.f32.tf32.tf32.f32 "
        "{%0,%1,%2,%3},{%4,%5,%6,%7},{%8,%9},{%0,%1,%2,%3};"
        : "+f"(c[0]), "+f"(c[1]), "+f"(c[2]), "+f"(c[3])
        : "r"(a[0]), "r"(a[1]), "r"(a[2]), "r"(a[3]), "r"(b0), "r"(b1));
}

// ---------------------------------------------------------------------------
// Kernel P: one-shot tf32 rounding pre-pass (src -> dst), grid-stride float4
// ---------------------------------------------------------------------------
__global__ void cvt_tf32_kernel(const float4* __restrict__ src,
                                float4* __restrict__ dst, int n4) {
    for (int i = blockIdx.x * blockDim.x + threadIdx.x; i < n4;
         i += gridDim.x * blockDim.x) {
        float4 v = src[i];
        v.x = f2tf_f(v.x); v.y = f2tf_f(v.y);
        v.z = f2tf_f(v.z); v.w = f2tf_f(v.w);
        dst[i] = v;
    }
}

// ---------------------------------------------------------------------------
// Kernel A: per-token gating + LoRA z = A_e . x
// ---------------------------------------------------------------------------
__global__ void gate_z_kernel(const float* __restrict__ x,
                              const float* __restrict__ gw,
                              const float* __restrict__ bias,
                              const float* __restrict__ lA) {
    const int n    = blockIdx.x;
    const int tid  = threadIdx.x;
    const int wid  = tid >> 5;
    const int lane = tid & 31;

    const float4* xr = reinterpret_cast<const float4*>(x + (size_t)n * HID);
    __shared__ float sred[4][RNK];
    __shared__ int   s_e;

    float a[NEXP] = {0.f, 0.f, 0.f, 0.f};
    const float4* gw4 = reinterpret_cast<const float4*>(gw);
    for (int h = tid; h < HID / 4; h += 128) {
        float4 xv = xr[h];
#pragma unroll
        for (int e = 0; e < NEXP; e++) {
            float4 g = gw4[e * (HID / 4) + h];
            a[e] += xv.x * g.x + xv.y * g.y + xv.z * g.z + xv.w * g.w;
        }
    }
#pragma unroll
    for (int e = 0; e < NEXP; e++)
#pragma unroll
        for (int off = 16; off > 0; off >>= 1)
            a[e] += __shfl_xor_sync(0xffffffffu, a[e], off);
    if (lane == 0)
#pragma unroll
        for (int e = 0; e < NEXP; e++) sred[wid][e] = a[e];
    __syncthreads();
    if (tid == 0) {
        float best = -3.4e38f; int be = 0;
#pragma unroll
        for (int e = 0; e < NEXP; e++) {
            float v = sred[0][e] + sred[1][e] + sred[2][e] + sred[3][e] + bias[e];
            if (v > best) { best = v; be = e; }
        }
        s_e = be;
        g_top1[n] = be;
    }
    __syncthreads();

    const int e = s_e;
    const float4* A4 = reinterpret_cast<const float4*>(lA + (size_t)e * RNK * HID);
    float z[RNK];
#pragma unroll
    for (int r = 0; r < RNK; r++) z[r] = 0.f;
    for (int h = tid; h < HID / 4; h += 128) {
        float4 xv = xr[h];
#pragma unroll
        for (int r = 0; r < RNK; r++) {
            float4 g = A4[r * (HID / 4) + h];
            z[r] += xv.x * g.x + xv.y * g.y + xv.z * g.z + xv.w * g.w;
        }
    }
#pragma unroll
    for (int r = 0; r < RNK; r++)
#pragma unroll
        for (int off = 16; off > 0; off >>= 1)
            z[r] += __shfl_xor_sync(0xffffffffu, z[r], off);
    __syncthreads();
    if (lane == 0)
#pragma unroll
        for (int r = 0; r < RNK; r++) sred[wid][r] = z[r];
    __syncthreads();
    if (tid < RNK)
        g_zs[(size_t)n * RNK + tid] =
            sred[0][tid] + sred[1][tid] + sred[2][tid] + sred[3][tid];
}

// ---------------------------------------------------------------------------
// Kernel B: tf32 mma.sync GEMM (pre-rounded operands) + fused LoRA epilogue
// 256 threads, CTA 128x128x32, warp 64x32, 3-stage cp.async.
// __launch_bounds__(256, 2): pin regs <=128 so 2 CTAs/SM co-reside
// (round-5 regression root cause: 140 regs -> 1 CTA/SM -> no latency hiding).
// ---------------------------------------------------------------------------
__device__ __forceinline__ void load_chunk(uint32_t base,
                                           const float* __restrict__ x,
                                           const float* __restrict__ w,
                                           int m0, int n0, int k0, int tid) {
    const int seg = tid & 7;       // 16B segment in 128B row
    const int r0  = tid >> 3;      // 0..31
    const float* ga = x + (size_t)(m0 + r0) * HID + k0 + seg * 4;
    const float* gb = w + (size_t)(n0 + r0) * HID + k0 + seg * 4;
#pragma unroll
    for (int i = 0; i < 4; i++) {
        const uint32_t off = (uint32_t)(r0 + i * 32) * ROWB + seg * 16;
        cp_async16(base + off,           ga + (size_t)i * 32 * HID);
        cp_async16(base + A_STAGE + off, gb + (size_t)i * 32 * HID);
    }
}

__global__ __launch_bounds__(256, 2)
void mma_gemm_kernel(const float* __restrict__ x,
                     const float* __restrict__ w,
                     const float* __restrict__ lB,
                     float* __restrict__ out) {
    extern __shared__ __align__(16) char dsm[];
    const uint32_t tiles = smem_u32(dsm);

    const int tid  = threadIdx.x;
    const int wid  = tid >> 5;
    const int lane = tid & 31;
    const int wm   = (wid & 1) * 64;     // warp m offset in CTA tile
    const int wn   = (wid >> 1) * 32;    // warp n offset
    const int m0   = blockIdx.y * BM;
    const int n0   = blockIdx.x * BN;

    // ldmatrix per-lane address offsets
    const int q = lane >> 3, r = lane & 7;
    uint32_t aoff[4], boff[4];
#pragma unroll
    for (int mt = 0; mt < 4; mt++)
        aoff[mt] = (uint32_t)(wm + mt * 16 + (q & 1) * 8 + r) * ROWB + (q >> 1) * 16;
#pragma unroll
    for (int nt = 0; nt < 4; nt++)
        boff[nt] = (uint32_t)(wn + nt * 8 + r) * ROWB + q * 16;

    float c[4][4][4];
#pragma unroll
    for (int i = 0; i < 4; i++)
#pragma unroll
        for (int j = 0; j < 4; j++)
#pragma unroll
            for (int t = 0; t < 4; t++) c[i][j][t] = 0.f;

    // prologue: stages 0, 1
    load_chunk(tiles + 0 * STAGE_BYTES, x, w, m0, n0, 0 * BK, tid);
    CP_COMMIT();
    load_chunk(tiles + 1 * STAGE_BYTES, x, w, m0, n0, 1 * BK, tid);
    CP_COMMIT();

    for (int k = 0; k < NCHUNK; k++) {
        if (k + 2 < NCHUNK)
            load_chunk(tiles + ((k + 2) % STAGES) * STAGE_BYTES,
                       x, w, m0, n0, (k + 2) * BK, tid);
        CP_COMMIT();           // empty groups at tail keep wait positional
        CP_WAIT2();            // chunk k resident
        __syncthreads();

        const uint32_t sA = tiles + (k % STAGES) * STAGE_BYTES;
        const uint32_t sB = sA + A_STAGE;

#pragma unroll
        for (int j = 0; j < 2; j++) {            // k-step pairs
            uint32_t Bf[4][4];
#pragma unroll
            for (int nt = 0; nt < 4; nt++)
                ldsm4(Bf[nt], sB + boff[nt] + j * 64);
#pragma unroll
            for (int half = 0; half < 2; half++) {
                uint32_t Af[4][4];
#pragma unroll
                for (int mt = 0; mt < 4; mt++)
                    ldsm4(Af[mt], sA + aoff[mt] + (2 * j + half) * 32);
#pragma unroll
                for (int mt = 0; mt < 4; mt++)
#pragma unroll
                    for (int nt = 0; nt < 4; nt++)
                        mma_tf32(c[mt][nt], Af[mt],
                                 Bf[nt][2 * half], Bf[nt][2 * half + 1]);
            }
        }
        __syncthreads();       // stage k%3 is refilled next iteration
    }

    // ---- epilogue: add LoRA delta, write out ----
    const int rowg = lane >> 2;          // 0..7
    const int colg = (lane & 3) * 2;
#pragma unroll
    for (int mt = 0; mt < 4; mt++) {
#pragma unroll
        for (int hr = 0; hr < 2; hr++) {
            const int row = m0 + wm + mt * 16 + hr * 8 + rowg;
            const int e   = g_top1[row];
            const float4* zz = reinterpret_cast<const float4*>(g_zs + (size_t)row * RNK);
            const float4 z0 = zz[0], z1 = zz[1];
            const float* lbe = lB + (size_t)e * HID * RNK;
            float* orow = out + (size_t)row * HID;
#pragma unroll
            for (int nt = 0; nt < 4; nt++) {
                const int col = n0 + wn + nt * 8 + colg;
                const float4* bp =
                    reinterpret_cast<const float4*>(lbe + (size_t)col * RNK);
                const float4 b0 = bp[0], b1 = bp[1];
                const float4* bq =
                    reinterpret_cast<const float4*>(lbe + (size_t)(col + 1) * RNK);
                const float4 q0 = bq[0], q1 = bq[1];
                float d0 = z0.x * b0.x + z0.y * b0.y + z0.z * b0.z + z0.w * b0.w
                         + z1.x * b1.x + z1.y * b1.y + z1.z * b1.z + z1.w * b1.w;
                float d1 = z0.x * q0.x + z0.y * q0.y + z0.z * q0.z + z0.w * q0.w
                         + z1.x * q1.x + z1.y * q1.y + z1.z * q1.z + z1.w * q1.w;
                float2 res = make_float2(c[mt][nt][hr * 2 + 0] + d0,
                                         c[mt][nt][hr * 2 + 1] + d1);
                *reinterpret_cast<float2*>(orow + col) = res;
            }
        }
    }
}

// ---------------------------------------------------------------------------
extern "C" void kernel_launch(void* const* d_in, const int* in_sizes, int n_in,
                              void* d_out, int out_size) {
    const float* x    = (const float*)d_in[0];
    const float* W_up = (const float*)d_in[1];
    const float* gw   = (const float*)d_in[2];
    const float* bias = (const float*)d_in[3];
    const float* lA   = (const float*)d_in[4];
    const float* lBm  = (const float*)d_in[5];
    float* out        = (float*)d_out;

    const int N = in_sizes[0] / HID;   // 16384 tokens

    cudaFuncSetAttribute(mma_gemm_kernel,
                         cudaFuncAttributeMaxDynamicSharedMemorySize, DYN_SMEM);
    cudaFuncSetAttribute(mma_gemm_kernel,
                         cudaFuncAttributePreferredSharedMemoryCarveout, 100);

    // device-symbol addresses (host-side; cheap, graph-capturable)
    float* xtf = nullptr;
    float* wtf = nullptr;
    cudaGetSymbolAddress((void**)&xtf, g_xtf);
    cudaGetSymbolAddress((void**)&wtf, g_wtf);

    // pre-pass: tf32-round x and W once
    const int n4x = N * HID / 4;
    const int n4w = HID * HID / 4;
    cvt_tf32_kernel<<<2048, 256>>>((const float4*)x,    (float4*)xtf, n4x);
    cvt_tf32_kernel<<<2048, 256>>>((const float4*)W_up, (float4*)wtf, n4w);

    gate_z_kernel<<<N, 128>>>(x, gw, bias, lA);

    dim3 grid(HID / BN, N / BM);       // (32, 128)
    mma_gemm_kernel<<<grid, 256, DYN_SMEM>>>(xtf, wtf, lBm, out);
}

// round 8
// speedup vs baseline: 2.1918x; 1.7772x over previous
#include <cuda_runtime.h>
#include <cuda_fp16.h>
#include <cstdint>

// ---------------- problem constants ----------------
#define HID   4096
#define NEXP  4
#define RNK   8
#define MAXN  16384

// ---------------- GEMM tiling (fp16 operands) ----------------
#define BM 128
#define BN 128
#define BK 64                         // fp16 elements per K-chunk (128 bytes)
#define NCHUNK (HID / BK)             // 64
#define ROWB   144                    // 64 halves (128B) + 16B pad
#define A_STAGE (BM * ROWB)           // 18432
#define STAGE_BYTES (2 * A_STAGE)     // 36864
#define STAGES 3
#define DYN_SMEM (STAGES * STAGE_BYTES)   // 110592

// scratch (allocation-free rule: __device__ globals live in bss)
__device__ float   g_zs[MAXN * RNK];
__device__ int     g_top1[MAXN];
__device__ __half  g_xh[(size_t)MAXN * HID];   // fp16 x   (128 MB)
__device__ __half  g_wh[(size_t)HID * HID];    // fp16 W   (32 MB)

// ---------------- PTX helpers ----------------
__device__ __forceinline__ uint32_t smem_u32(const void* p) {
    uint32_t a;
    asm("{ .reg .u64 t; cvta.to.shared.u64 t, %1; cvt.u32.u64 %0, t; }"
        : "=r"(a) : "l"(p));
    return a;
}
__device__ __forceinline__ void cp_async16(uint32_t dst, const void* src) {
    asm volatile("cp.async.cg.shared.global [%0], [%1], 16;"
                 :: "r"(dst), "l"(src) : "memory");
}
#define CP_COMMIT() asm volatile("cp.async.commit_group;" ::: "memory")
#define CP_WAIT2()  asm volatile("cp.async.wait_group 2;"  ::: "memory")

__device__ __forceinline__ void ldsm4(uint32_t* d, uint32_t addr) {
    asm volatile("ldmatrix.sync.aligned.m8n8.x4.shared.b16 {%0,%1,%2,%3}, [%4];"
                 : "=r"(d[0]), "=r"(d[1]), "=r"(d[2]), "=r"(d[3]) : "r"(addr));
}
__device__ __forceinline__ uint32_t pack_h2(float lo, float hi) {
    uint32_t r;
    asm("cvt.rn.f16x2.f32 %0, %1, %2;" : "=r"(r) : "f"(hi), "f"(lo));
    return r;
}
__device__ __forceinline__ void mma_f16(float* c, const uint32_t* a,
                                        uint32_t b0, uint32_t b1) {
    asm volatile(
        "mma.sync.aligned.m16n8k16.row.col.f32.f16.f16.f32 "
        "{%0,%1,%2,%3},{%4,%5,%6,%7},{%8,%9},{%0,%1,%2,%3};"
        : "+f"(c[0]), "+f"(c[1]), "+f"(c[2]), "+f"(c[3])
        : "r"(a[0]), "r"(a[1]), "r"(a[2]), "r"(a[3]), "r"(b0), "r"(b1));
}

// ---------------------------------------------------------------------------
// Kernel P: one-shot f32 -> fp16 pre-pass. Each thread: 8 floats -> 8 halves.
// ---------------------------------------------------------------------------
__global__ void cvt_f16_kernel(const float4* __restrict__ src,
                               uint4* __restrict__ dst, int n8) {
    for (int i = blockIdx.x * blockDim.x + threadIdx.x; i < n8;
         i += gridDim.x * blockDim.x) {
        float4 v0 = src[2 * i], v1 = src[2 * i + 1];
        uint4 o;
        o.x = pack_h2(v0.x, v0.y);
        o.y = pack_h2(v0.z, v0.w);
        o.z = pack_h2(v1.x, v1.y);
        o.w = pack_h2(v1.z, v1.w);
        dst[i] = o;
    }
}

// ---------------------------------------------------------------------------
// Kernel A: per-token gating + LoRA z = A_e . x  (fp32, exact)
// ---------------------------------------------------------------------------
__global__ void gate_z_kernel(const float* __restrict__ x,
                              const float* __restrict__ gw,
                              const float* __restrict__ bias,
                              const float* __restrict__ lA) {
    const int n    = blockIdx.x;
    const int tid  = threadIdx.x;
    const int wid  = tid >> 5;
    const int lane = tid & 31;

    const float4* xr = reinterpret_cast<const float4*>(x + (size_t)n * HID);
    __shared__ float sred[4][RNK];
    __shared__ int   s_e;

    float a[NEXP] = {0.f, 0.f, 0.f, 0.f};
    const float4* gw4 = reinterpret_cast<const float4*>(gw);
    for (int h = tid; h < HID / 4; h += 128) {
        float4 xv = xr[h];
#pragma unroll
        for (int e = 0; e < NEXP; e++) {
            float4 g = gw4[e * (HID / 4) + h];
            a[e] += xv.x * g.x + xv.y * g.y + xv.z * g.z + xv.w * g.w;
        }
    }
#pragma unroll
    for (int e = 0; e < NEXP; e++)
#pragma unroll
        for (int off = 16; off > 0; off >>= 1)
            a[e] += __shfl_xor_sync(0xffffffffu, a[e], off);
    if (lane == 0)
#pragma unroll
        for (int e = 0; e < NEXP; e++) sred[wid][e] = a[e];
    __syncthreads();
    if (tid == 0) {
        float best = -3.4e38f; int be = 0;
#pragma unroll
        for (int e = 0; e < NEXP; e++) {
            float v = sred[0][e] + sred[1][e] + sred[2][e] + sred[3][e] + bias[e];
            if (v > best) { best = v; be = e; }
        }
        s_e = be;
        g_top1[n] = be;
    }
    __syncthreads();

    const int e = s_e;
    const float4* A4 = reinterpret_cast<const float4*>(lA + (size_t)e * RNK * HID);
    float z[RNK];
#pragma unroll
    for (int r = 0; r < RNK; r++) z[r] = 0.f;
    for (int h = tid; h < HID / 4; h += 128) {
        float4 xv = xr[h];
#pragma unroll
        for (int r = 0; r < RNK; r++) {
            float4 g = A4[r * (HID / 4) + h];
            z[r] += xv.x * g.x + xv.y * g.y + xv.z * g.z + xv.w * g.w;
        }
    }
#pragma unroll
    for (int r = 0; r < RNK; r++)
#pragma unroll
        for (int off = 16; off > 0; off >>= 1)
            z[r] += __shfl_xor_sync(0xffffffffu, z[r], off);
    __syncthreads();
    if (lane == 0)
#pragma unroll
        for (int r = 0; r < RNK; r++) sred[wid][r] = z[r];
    __syncthreads();
    if (tid < RNK)
        g_zs[(size_t)n * RNK + tid] =
            sred[0][tid] + sred[1][tid] + sred[2][tid] + sred[3][tid];
}

// ---------------------------------------------------------------------------
// Kernel B: fp16 m16n8k16 mma.sync GEMM + fused LoRA epilogue
// 256 threads, CTA 128x128x64, warp 64x32, 3-stage cp.async, 2 CTAs/SM.
// ---------------------------------------------------------------------------
__device__ __forceinline__ void load_chunk(uint32_t base,
                                           const __half* __restrict__ x,
                                           const __half* __restrict__ w,
                                           int m0, int n0, int k0, int tid) {
    const int seg = tid & 7;       // 16B segment in 128B row (8 halves)
    const int r0  = tid >> 3;      // 0..31
    const __half* ga = x + (size_t)(m0 + r0) * HID + k0 + seg * 8;
    const __half* gb = w + (size_t)(n0 + r0) * HID + k0 + seg * 8;
#pragma unroll
    for (int i = 0; i < 4; i++) {
        const uint32_t off = (uint32_t)(r0 + i * 32) * ROWB + seg * 16;
        cp_async16(base + off,           ga + (size_t)i * 32 * HID);
        cp_async16(base + A_STAGE + off, gb + (size_t)i * 32 * HID);
    }
}

__global__ __launch_bounds__(256, 2)
void mma_gemm_kernel(const __half* __restrict__ x,
                     const __half* __restrict__ w,
                     const float* __restrict__ lB,
                     float* __restrict__ out) {
    extern __shared__ __align__(16) char dsm[];
    const uint32_t tiles = smem_u32(dsm);

    const int tid  = threadIdx.x;
    const int wid  = tid >> 5;
    const int lane = tid & 31;
    const int wm   = (wid & 1) * 64;     // warp m offset
    const int wn   = (wid >> 1) * 32;    // warp n offset
    const int m0   = blockIdx.y * BM;
    const int n0   = blockIdx.x * BN;

    // ldmatrix lane addresses
    // A (x4, one mt + one k16-step): rows lane&15, col-halves (lane>>4)*8
    uint32_t aoff[4];
#pragma unroll
    for (int mt = 0; mt < 4; mt++)
        aoff[mt] = (uint32_t)(wm + mt * 16 + (lane & 15)) * ROWB + (lane >> 4) * 16;
    // B (x4, one nt + k32): rows lane&7, 4 matrices at k 0-7/8-15/16-23/24-31
    uint32_t boff[4];
#pragma unroll
    for (int nt = 0; nt < 4; nt++)
        boff[nt] = (uint32_t)(wn + nt * 8 + (lane & 7)) * ROWB + (lane >> 3) * 16;

    float c[4][4][4];
#pragma unroll
    for (int i = 0; i < 4; i++)
#pragma unroll
        for (int j = 0; j < 4; j++)
#pragma unroll
            for (int t = 0; t < 4; t++) c[i][j][t] = 0.f;

    // prologue
    load_chunk(tiles + 0 * STAGE_BYTES, x, w, m0, n0, 0 * BK, tid);
    CP_COMMIT();
    load_chunk(tiles + 1 * STAGE_BYTES, x, w, m0, n0, 1 * BK, tid);
    CP_COMMIT();

    for (int k = 0; k < NCHUNK; k++) {
        if (k + 2 < NCHUNK)
            load_chunk(tiles + ((k + 2) % STAGES) * STAGE_BYTES,
                       x, w, m0, n0, (k + 2) * BK, tid);
        CP_COMMIT();
        CP_WAIT2();
        __syncthreads();

        const uint32_t sA = tiles + (k % STAGES) * STAGE_BYTES;
        const uint32_t sB = sA + A_STAGE;

#pragma unroll
        for (int h = 0; h < 2; h++) {                 // two k32 halves
            uint32_t Bf[4][4];
#pragma unroll
            for (int nt = 0; nt < 4; nt++)
                ldsm4(Bf[nt], sB + boff[nt] + h * 64);
#pragma unroll
            for (int ks = 0; ks < 2; ks++) {          // two k16 steps per half
                uint32_t Af[4][4];
#pragma unroll
                for (int mt = 0; mt < 4; mt++)
                    ldsm4(Af[mt], sA + aoff[mt] + (h * 2 + ks) * 32);
#pragma unroll
                for (int mt = 0; mt < 4; mt++)
#pragma unroll
                    for (int nt = 0; nt < 4; nt++)
                        mma_f16(c[mt][nt], Af[mt],
                                Bf[nt][2 * ks], Bf[nt][2 * ks + 1]);
            }
        }
        __syncthreads();
    }

    // ---- epilogue: add LoRA delta, write out ----
    const int rowg = lane >> 2;          // 0..7
    const int colg = (lane & 3) * 2;
#pragma unroll
    for (int mt = 0; mt < 4; mt++) {
#pragma unroll
        for (int hr = 0; hr < 2; hr++) {
            const int row = m0 + wm + mt * 16 + hr * 8 + rowg;
            const int e   = g_top1[row];
            const float4* zz = reinterpret_cast<const float4*>(g_zs + (size_t)row * RNK);
            const float4 z0 = zz[0], z1 = zz[1];
            const float* lbe = lB + (size_t)e * HID * RNK;
            float* orow = out + (size_t)row * HID;
#pragma unroll
            for (int nt = 0; nt < 4; nt++) {
                const int col = n0 + wn + nt * 8 + colg;
                const float4* bp =
                    reinterpret_cast<const float4*>(lbe + (size_t)col * RNK);
                const float4 b0 = bp[0], b1 = bp[1];
                const float4* bq =
                    reinterpret_cast<const float4*>(lbe + (size_t)(col + 1) * RNK);
                const float4 q0 = bq[0], q1 = bq[1];
                float d0 = z0.x * b0.x + z0.y * b0.y + z0.z * b0.z + z0.w * b0.w
                         + z1.x * b1.x + z1.y * b1.y + z1.z * b1.z + z1.w * b1.w;
                float d1 = z0.x * q0.x + z0.y * q0.y + z0.z * q0.z + z0.w * q0.w
                         + z1.x * q1.x + z1.y * q1.y + z1.z * q1.z + z1.w * q1.w;
                float2 res = make_float2(c[mt][nt][hr * 2 + 0] + d0,
                                         c[mt][nt][hr * 2 + 1] + d1);
                *reinterpret_cast<float2*>(orow + col) = res;
            }
        }
    }
}

// ---------------------------------------------------------------------------
extern "C" void kernel_launch(void* const* d_in, const int* in_sizes, int n_in,
                              void* d_out, int out_size) {
    const float* x    = (const float*)d_in[0];
    const float* W_up = (const float*)d_in[1];
    const float* gw   = (const float*)d_in[2];
    const float* bias = (const float*)d_in[3];
    const float* lA   = (const float*)d_in[4];
    const float* lBm  = (const float*)d_in[5];
    float* out        = (float*)d_out;

    const int N = in_sizes[0] / HID;   // 16384 tokens

    cudaFuncSetAttribute(mma_gemm_kernel,
                         cudaFuncAttributeMaxDynamicSharedMemorySize, DYN_SMEM);
    cudaFuncSetAttribute(mma_gemm_kernel,
                         cudaFuncAttributePreferredSharedMemoryCarveout, 100);

    __half* xh = nullptr;
    __half* wh = nullptr;
    cudaGetSymbolAddress((void**)&xh, g_xh);
    cudaGetSymbolAddress((void**)&wh, g_wh);

    // pre-pass: f32 -> fp16 round once
    const int n8x = N * HID / 8;
    const int n8w = HID * HID / 8;
    cvt_f16_kernel<<<2048, 256>>>((const float4*)x,    (uint4*)xh, n8x);
    cvt_f16_kernel<<<2048, 256>>>((const float4*)W_up, (uint4*)wh, n8w);

    gate_z_kernel<<<N, 128>>>(x, gw, bias, lA);

    dim3 grid(HID / BN, N / BM);       // (32, 128)
    mma_gemm_kernel<<<grid, 256, DYN_SMEM>>>(xh, wh, lBm, out);
}

// round 9
// speedup vs baseline: 2.2587x; 1.0305x over previous
#include <cuda_runtime.h>
#include <cuda_fp16.h>
#include <cstdint>

// ---------------- problem constants ----------------
#define HID   4096
#define NEXP  4
#define RNK   8
#define MAXN  16384

// ---------------- GEMM tiling (fp16 operands) ----------------
#define BM 128
#define BN 128
#define BK 64                         // fp16 elements per K-chunk (128 bytes)
#define NCHUNK (HID / BK)             // 64
#define ROWB   144                    // 64 halves (128B) + 16B pad
#define A_STAGE (BM * ROWB)           // 18432
#define STAGE_BYTES (2 * A_STAGE)     // 36864
#define STAGES 3
#define DYN_SMEM (STAGES * STAGE_BYTES)   // 110592

// scratch (allocation-free rule: __device__ globals live in bss)
__device__ float   g_zs[MAXN * RNK];
__device__ int     g_top1[MAXN];
__device__ __half  g_xh[(size_t)MAXN * HID];   // fp16 x   (128 MB)
__device__ __half  g_wh[(size_t)HID * HID];    // fp16 W   (32 MB)

// ---------------- PTX helpers ----------------
__device__ __forceinline__ uint32_t smem_u32(const void* p) {
    uint32_t a;
    asm("{ .reg .u64 t; cvta.to.shared.u64 t, %1; cvt.u32.u64 %0, t; }"
        : "=r"(a) : "l"(p));
    return a;
}
__device__ __forceinline__ void cp_async16(uint32_t dst, const void* src) {
    asm volatile("cp.async.cg.shared.global [%0], [%1], 16;"
                 :: "r"(dst), "l"(src) : "memory");
}
#define CP_COMMIT() asm volatile("cp.async.commit_group;" ::: "memory")
#define CP_WAIT1()  asm volatile("cp.async.wait_group 1;"  ::: "memory")

__device__ __forceinline__ void ldsm4(uint32_t* d, uint32_t addr) {
    asm volatile("ldmatrix.sync.aligned.m8n8.x4.shared.b16 {%0,%1,%2,%3}, [%4];"
                 : "=r"(d[0]), "=r"(d[1]), "=r"(d[2]), "=r"(d[3]) : "r"(addr));
}
__device__ __forceinline__ uint32_t pack_h2(float lo, float hi) {
    uint32_t r;
    asm("cvt.rn.f16x2.f32 %0, %1, %2;" : "=r"(r) : "f"(hi), "f"(lo));
    return r;
}
__device__ __forceinline__ void mma_f16(float* c, const uint32_t* a,
                                        uint32_t b0, uint32_t b1) {
    asm volatile(
        "mma.sync.aligned.m16n8k16.row.col.f32.f16.f16.f32 "
        "{%0,%1,%2,%3},{%4,%5,%6,%7},{%8,%9},{%0,%1,%2,%3};"
        : "+f"(c[0]), "+f"(c[1]), "+f"(c[2]), "+f"(c[3])
        : "r"(a[0]), "r"(a[1]), "r"(a[2]), "r"(a[3]), "r"(b0), "r"(b1));
}

// ---------------------------------------------------------------------------
// Kernel P: one-shot f32 -> fp16 pre-pass for W. x is converted in gate_z.
// ---------------------------------------------------------------------------
__global__ void cvt_f16_kernel(const float4* __restrict__ src,
                               uint4* __restrict__ dst, int n8) {
    for (int i = blockIdx.x * blockDim.x + threadIdx.x; i < n8;
         i += gridDim.x * blockDim.x) {
        float4 v0 = src[2 * i], v1 = src[2 * i + 1];
        uint4 o;
        o.x = pack_h2(v0.x, v0.y);
        o.y = pack_h2(v0.z, v0.w);
        o.z = pack_h2(v1.x, v1.y);
        o.w = pack_h2(v1.z, v1.w);
        dst[i] = o;
    }
}

// ---------------------------------------------------------------------------
// Kernel A: per-token gating + LoRA z = A_e . x + fused f16(x) conversion
// ---------------------------------------------------------------------------
__global__ void gate_z_kernel(const float* __restrict__ x,
                              const float* __restrict__ gw,
                              const float* __restrict__ bias,
                              const float* __restrict__ lA) {
    const int n    = blockIdx.x;
    const int tid  = threadIdx.x;
    const int wid  = tid >> 5;
    const int lane = tid & 31;

    const float4* xr = reinterpret_cast<const float4*>(x + (size_t)n * HID);
    uint2* xh2 = reinterpret_cast<uint2*>(g_xh + (size_t)n * HID);
    __shared__ float sred[4][RNK];
    __shared__ int   s_e;

    float a[NEXP] = {0.f, 0.f, 0.f, 0.f};
    const float4* gw4 = reinterpret_cast<const float4*>(gw);
    for (int h = tid; h < HID / 4; h += 128) {
        float4 xv = xr[h];
        // fused fp16 conversion of x (saves a separate 256MB-read pass)
        uint2 o;
        o.x = pack_h2(xv.x, xv.y);
        o.y = pack_h2(xv.z, xv.w);
        xh2[h] = o;
#pragma unroll
        for (int e = 0; e < NEXP; e++) {
            float4 g = gw4[e * (HID / 4) + h];
            a[e] += xv.x * g.x + xv.y * g.y + xv.z * g.z + xv.w * g.w;
        }
    }
#pragma unroll
    for (int e = 0; e < NEXP; e++)
#pragma unroll
        for (int off = 16; off > 0; off >>= 1)
            a[e] += __shfl_xor_sync(0xffffffffu, a[e], off);
    if (lane == 0)
#pragma unroll
        for (int e = 0; e < NEXP; e++) sred[wid][e] = a[e];
    __syncthreads();
    if (tid == 0) {
        float best = -3.4e38f; int be = 0;
#pragma unroll
        for (int e = 0; e < NEXP; e++) {
            float v = sred[0][e] + sred[1][e] + sred[2][e] + sred[3][e] + bias[e];
            if (v > best) { best = v; be = e; }
        }
        s_e = be;
        g_top1[n] = be;
    }
    __syncthreads();

    const int e = s_e;
    const float4* A4 = reinterpret_cast<const float4*>(lA + (size_t)e * RNK * HID);
    float z[RNK];
#pragma unroll
    for (int r = 0; r < RNK; r++) z[r] = 0.f;
    for (int h = tid; h < HID / 4; h += 128) {
        float4 xv = xr[h];
#pragma unroll
        for (int r = 0; r < RNK; r++) {
            float4 g = A4[r * (HID / 4) + h];
            z[r] += xv.x * g.x + xv.y * g.y + xv.z * g.z + xv.w * g.w;
        }
    }
#pragma unroll
    for (int r = 0; r < RNK; r++)
#pragma unroll
        for (int off = 16; off > 0; off >>= 1)
            z[r] += __shfl_xor_sync(0xffffffffu, z[r], off);
    __syncthreads();
    if (lane == 0)
#pragma unroll
        for (int r = 0; r < RNK; r++) sred[wid][r] = z[r];
    __syncthreads();
    if (tid < RNK)
        g_zs[(size_t)n * RNK + tid] =
            sred[0][tid] + sred[1][tid] + sred[2][tid] + sred[3][tid];
}

// ---------------------------------------------------------------------------
// Kernel B: fp16 m16n8k16 mma.sync GEMM + fused LoRA epilogue
// 256 threads, CTA 128x128x64, warp 64x32, 3-stage cp.async, 2 CTAs/SM.
// Single __syncthreads per chunk:
//   wait_group(1) [chunk k resident] -> barrier [also: chunk k-1 reads done]
//   -> issue loads chunk k+2 (into chunk k-1's stage) -> compute chunk k.
// ---------------------------------------------------------------------------
__device__ __forceinline__ void load_chunk(uint32_t base,
                                           const __half* __restrict__ x,
                                           const __half* __restrict__ w,
                                           int m0, int n0, int k0, int tid) {
    const int seg = tid & 7;       // 16B segment in 128B row (8 halves)
    const int r0  = tid >> 3;      // 0..31
    const __half* ga = x + (size_t)(m0 + r0) * HID + k0 + seg * 8;
    const __half* gb = w + (size_t)(n0 + r0) * HID + k0 + seg * 8;
#pragma unroll
    for (int i = 0; i < 4; i++) {
        const uint32_t off = (uint32_t)(r0 + i * 32) * ROWB + seg * 16;
        cp_async16(base + off,           ga + (size_t)i * 32 * HID);
        cp_async16(base + A_STAGE + off, gb + (size_t)i * 32 * HID);
    }
}

__global__ __launch_bounds__(256, 2)
void mma_gemm_kernel(const __half* __restrict__ x,
                     const __half* __restrict__ w,
                     const float* __restrict__ lB,
                     float* __restrict__ out) {
    extern __shared__ __align__(16) char dsm[];
    const uint32_t tiles = smem_u32(dsm);

    const int tid  = threadIdx.x;
    const int wid  = tid >> 5;
    const int lane = tid & 31;
    const int wm   = (wid & 1) * 64;     // warp m offset
    const int wn   = (wid >> 1) * 32;    // warp n offset
    const int m0   = blockIdx.y * BM;
    const int n0   = blockIdx.x * BN;

    // ldmatrix lane addresses
    uint32_t aoff[4];
#pragma unroll
    for (int mt = 0; mt < 4; mt++)
        aoff[mt] = (uint32_t)(wm + mt * 16 + (lane & 15)) * ROWB + (lane >> 4) * 16;
    uint32_t boff[4];
#pragma unroll
    for (int nt = 0; nt < 4; nt++)
        boff[nt] = (uint32_t)(wn + nt * 8 + (lane & 7)) * ROWB + (lane >> 3) * 16;

    float c[4][4][4];
#pragma unroll
    for (int i = 0; i < 4; i++)
#pragma unroll
        for (int j = 0; j < 4; j++)
#pragma unroll
            for (int t = 0; t < 4; t++) c[i][j][t] = 0.f;

    // prologue: chunks 0, 1 into stages 0, 1
    load_chunk(tiles + 0 * STAGE_BYTES, x, w, m0, n0, 0 * BK, tid);
    CP_COMMIT();
    load_chunk(tiles + 1 * STAGE_BYTES, x, w, m0, n0, 1 * BK, tid);
    CP_COMMIT();

    for (int k = 0; k < NCHUNK; k++) {
        CP_WAIT1();            // commit #k drained -> chunk k resident
        __syncthreads();       // publish chunk k; all reads of chunk k-1 done
        if (k + 2 < NCHUNK)
            load_chunk(tiles + ((k + 2) % STAGES) * STAGE_BYTES,
                       x, w, m0, n0, (k + 2) * BK, tid);
        CP_COMMIT();           // exactly one group per iter (empty at tail)

        const uint32_t sA = tiles + (k % STAGES) * STAGE_BYTES;
        const uint32_t sB = sA + A_STAGE;

#pragma unroll
        for (int h = 0; h < 2; h++) {                 // two k32 halves
            uint32_t Bf[4][4];
#pragma unroll
            for (int nt = 0; nt < 4; nt++)
                ldsm4(Bf[nt], sB + boff[nt] + h * 64);
#pragma unroll
            for (int ks = 0; ks < 2; ks++) {          // two k16 steps per half
                uint32_t Af[4][4];
#pragma unroll
                for (int mt = 0; mt < 4; mt++)
                    ldsm4(Af[mt], sA + aoff[mt] + (h * 2 + ks) * 32);
#pragma unroll
                for (int mt = 0; mt < 4; mt++)
#pragma unroll
                    for (int nt = 0; nt < 4; nt++)
                        mma_f16(c[mt][nt], Af[mt],
                                Bf[nt][2 * ks], Bf[nt][2 * ks + 1]);
            }
        }
    }

    // ---- epilogue: add LoRA delta, write out ----
    const int rowg = lane >> 2;          // 0..7
    const int colg = (lane & 3) * 2;
#pragma unroll
    for (int mt = 0; mt < 4; mt++) {
#pragma unroll
        for (int hr = 0; hr < 2; hr++) {
            const int row = m0 + wm + mt * 16 + hr * 8 + rowg;
            const int e   = g_top1[row];
            const float4* zz = reinterpret_cast<const float4*>(g_zs + (size_t)row * RNK);
            const float4 z0 = zz[0], z1 = zz[1];
            const float* lbe = lB + (size_t)e * HID * RNK;
            float* orow = out + (size_t)row * HID;
#pragma unroll
            for (int nt = 0; nt < 4; nt++) {
                const int col = n0 + wn + nt * 8 + colg;
                const float4* bp =
                    reinterpret_cast<const float4*>(lbe + (size_t)col * RNK);
                const float4 b0 = bp[0], b1 = bp[1];
                const float4* bq =
                    reinterpret_cast<const float4*>(lbe + (size_t)(col + 1) * RNK);
                const float4 q0 = bq[0], q1 = bq[1];
                float d0 = z0.x * b0.x + z0.y * b0.y + z0.z * b0.z + z0.w * b0.w
                         + z1.x * b1.x + z1.y * b1.y + z1.z * b1.z + z1.w * b1.w;
                float d1 = z0.x * q0.x + z0.y * q0.y + z0.z * q0.z + z0.w * q0.w
                         + z1.x * q1.x + z1.y * q1.y + z1.z * q1.z + z1.w * q1.w;
                float2 res = make_float2(c[mt][nt][hr * 2 + 0] + d0,
                                         c[mt][nt][hr * 2 + 1] + d1);
                *reinterpret_cast<float2*>(orow + col) = res;
            }
        }
    }
}

// ---------------------------------------------------------------------------
extern "C" void kernel_launch(void* const* d_in, const int* in_sizes, int n_in,
                              void* d_out, int out_size) {
    const float* x    = (const float*)d_in[0];
    const float* W_up = (const float*)d_in[1];
    const float* gw   = (const float*)d_in[2];
    const float* bias = (const float*)d_in[3];
    const float* lA   = (const float*)d_in[4];
    const float* lBm  = (const float*)d_in[5];
    float* out        = (float*)d_out;

    const int N = in_sizes[0] / HID;   // 16384 tokens

    cudaFuncSetAttribute(mma_gemm_kernel,
                         cudaFuncAttributeMaxDynamicSharedMemorySize, DYN_SMEM);
    cudaFuncSetAttribute(mma_gemm_kernel,
                         cudaFuncAttributePreferredSharedMemoryCarveout, 100);

    __half* xh = nullptr;
    __half* wh = nullptr;
    cudaGetSymbolAddress((void**)&xh, g_xh);
    cudaGetSymbolAddress((void**)&wh, g_wh);

    // W pre-pass; x converted inside gate_z_kernel
    const int n8w = HID * HID / 8;
    cvt_f16_kernel<<<2048, 256>>>((const float4*)W_up, (uint4*)wh, n8w);

    gate_z_kernel<<<N, 128>>>(x, gw, bias, lA);

    dim3 grid(HID / BN, N / BM);       // (32, 128)
    mma_gemm_kernel<<<grid, 256, DYN_SMEM>>>(xh, wh, lBm, out);
}

// round 10
// speedup vs baseline: 2.4814x; 1.0986x over previous
#include <cuda_runtime.h>
#include <cuda_fp16.h>
#include <cstdint>

// ---------------- problem constants ----------------
#define HID   4096
#define NEXP  4
#define RNK   8
#define MAXN  16384

// ---------------- GEMM tiling (fp16 operands) ----------------
#define BM 128
#define BN 128
#define BK 64                         // fp16 elements per K-chunk (128 bytes)
#define NCHUNK (HID / BK)             // 64
#define ROWB   144                    // 64 halves (128B) + 16B pad
#define A_STAGE (BM * ROWB)           // 18432
#define STAGE_BYTES (2 * A_STAGE)     // 36864
#define STAGES 3
#define DYN_SMEM (STAGES * STAGE_BYTES)   // 110592

// scratch (allocation-free rule: __device__ globals live in bss)
__device__ float   g_zs[MAXN * RNK];
__device__ int     g_top1[MAXN];
__device__ __half  g_xh[(size_t)MAXN * HID];   // fp16 x   (128 MB)
__device__ __half  g_wh[(size_t)HID * HID];    // fp16 W   (32 MB)

// ---------------- PTX helpers ----------------
__device__ __forceinline__ uint32_t smem_u32(const void* p) {
    uint32_t a;
    asm("{ .reg .u64 t; cvta.to.shared.u64 t, %1; cvt.u32.u64 %0, t; }"
        : "=r"(a) : "l"(p));
    return a;
}
__device__ __forceinline__ void cp_async16(uint32_t dst, const void* src) {
    asm volatile("cp.async.cg.shared.global [%0], [%1], 16;"
                 :: "r"(dst), "l"(src) : "memory");
}
#define CP_COMMIT() asm volatile("cp.async.commit_group;" ::: "memory")
#define CP_WAIT1()  asm volatile("cp.async.wait_group 1;"  ::: "memory")

__device__ __forceinline__ void ldsm4(uint32_t* d, uint32_t addr) {
    asm volatile("ldmatrix.sync.aligned.m8n8.x4.shared.b16 {%0,%1,%2,%3}, [%4];"
                 : "=r"(d[0]), "=r"(d[1]), "=r"(d[2]), "=r"(d[3]) : "r"(addr));
}
__device__ __forceinline__ uint32_t pack_h2(float lo, float hi) {
    uint32_t r;
    asm("cvt.rn.f16x2.f32 %0, %1, %2;" : "=r"(r) : "f"(hi), "f"(lo));
    return r;
}
__device__ __forceinline__ void mma_f16(float* c, const uint32_t* a,
                                        uint32_t b0, uint32_t b1) {
    asm volatile(
        "mma.sync.aligned.m16n8k16.row.col.f32.f16.f16.f32 "
        "{%0,%1,%2,%3},{%4,%5,%6,%7},{%8,%9},{%0,%1,%2,%3};"
        : "+f"(c[0]), "+f"(c[1]), "+f"(c[2]), "+f"(c[3])
        : "r"(a[0]), "r"(a[1]), "r"(a[2]), "r"(a[3]), "r"(b0), "r"(b1));
}

// ---------------------------------------------------------------------------
// Kernel P: one-shot f32 -> fp16 pre-pass for W. x is converted in gate_z.
// ---------------------------------------------------------------------------
__global__ void cvt_f16_kernel(const float4* __restrict__ src,
                               uint4* __restrict__ dst, int n8) {
    for (int i = blockIdx.x * blockDim.x + threadIdx.x; i < n8;
         i += gridDim.x * blockDim.x) {
        float4 v0 = src[2 * i], v1 = src[2 * i + 1];
        uint4 o;
        o.x = pack_h2(v0.x, v0.y);
        o.y = pack_h2(v0.z, v0.w);
        o.z = pack_h2(v1.x, v1.y);
        o.w = pack_h2(v1.z, v1.w);
        dst[i] = o;
    }
}

// ---------------------------------------------------------------------------
// Kernel A: per-token gating + LoRA z = A_e . x + fused f16(x) conversion
// ---------------------------------------------------------------------------
__global__ void gate_z_kernel(const float* __restrict__ x,
                              const float* __restrict__ gw,
                              const float* __restrict__ bias,
                              const float* __restrict__ lA) {
    const int n    = blockIdx.x;
    const int tid  = threadIdx.x;
    const int wid  = tid >> 5;
    const int lane = tid & 31;

    const float4* xr = reinterpret_cast<const float4*>(x + (size_t)n * HID);
    uint2* xh2 = reinterpret_cast<uint2*>(g_xh + (size_t)n * HID);
    __shared__ float sred[4][RNK];
    __shared__ int   s_e;

    float a[NEXP] = {0.f, 0.f, 0.f, 0.f};
    const float4* gw4 = reinterpret_cast<const float4*>(gw);
    for (int h = tid; h < HID / 4; h += 128) {
        float4 xv = xr[h];
        uint2 o;
        o.x = pack_h2(xv.x, xv.y);
        o.y = pack_h2(xv.z, xv.w);
        xh2[h] = o;
#pragma unroll
        for (int e = 0; e < NEXP; e++) {
            float4 g = gw4[e * (HID / 4) + h];
            a[e] += xv.x * g.x + xv.y * g.y + xv.z * g.z + xv.w * g.w;
        }
    }
#pragma unroll
    for (int e = 0; e < NEXP; e++)
#pragma unroll
        for (int off = 16; off > 0; off >>= 1)
            a[e] += __shfl_xor_sync(0xffffffffu, a[e], off);
    if (lane == 0)
#pragma unroll
        for (int e = 0; e < NEXP; e++) sred[wid][e] = a[e];
    __syncthreads();
    if (tid == 0) {
        float best = -3.4e38f; int be = 0;
#pragma unroll
        for (int e = 0; e < NEXP; e++) {
            float v = sred[0][e] + sred[1][e] + sred[2][e] + sred[3][e] + bias[e];
            if (v > best) { best = v; be = e; }
        }
        s_e = be;
        g_top1[n] = be;
    }
    __syncthreads();

    const int e = s_e;
    const float4* A4 = reinterpret_cast<const float4*>(lA + (size_t)e * RNK * HID);
    float z[RNK];
#pragma unroll
    for (int r = 0; r < RNK; r++) z[r] = 0.f;
    for (int h = tid; h < HID / 4; h += 128) {
        float4 xv = xr[h];
#pragma unroll
        for (int r = 0; r < RNK; r++) {
            float4 g = A4[r * (HID / 4) + h];
            z[r] += xv.x * g.x + xv.y * g.y + xv.z * g.z + xv.w * g.w;
        }
    }
#pragma unroll
    for (int r = 0; r < RNK; r++)
#pragma unroll
        for (int off = 16; off > 0; off >>= 1)
            z[r] += __shfl_xor_sync(0xffffffffu, z[r], off);
    __syncthreads();
    if (lane == 0)
#pragma unroll
        for (int r = 0; r < RNK; r++) sred[wid][r] = z[r];
    __syncthreads();
    if (tid < RNK)
        g_zs[(size_t)n * RNK + tid] =
            sred[0][tid] + sred[1][tid] + sred[2][tid] + sred[3][tid];
}

// ---------------------------------------------------------------------------
// Kernel B: fp16 m16n8k16 GEMM, software-pipelined fragments.
// 256 threads, CTA 128x128x64, warp 64x32, 3-stage cp.async, 2 CTAs/SM.
// Inner schedule (per chunk): no MMA group depends on a just-issued ldmatrix.
// ---------------------------------------------------------------------------
__device__ __forceinline__ void load_chunk(uint32_t base,
                                           const __half* __restrict__ x,
                                           const __half* __restrict__ w,
                                           int m0, int n0, int k0, int tid) {
    const int seg = tid & 7;       // 16B segment in 128B row (8 halves)
    const int r0  = tid >> 3;      // 0..31
    const __half* ga = x + (size_t)(m0 + r0) * HID + k0 + seg * 8;
    const __half* gb = w + (size_t)(n0 + r0) * HID + k0 + seg * 8;
#pragma unroll
    for (int i = 0; i < 4; i++) {
        const uint32_t off = (uint32_t)(r0 + i * 32) * ROWB + seg * 16;
        cp_async16(base + off,           ga + (size_t)i * 32 * HID);
        cp_async16(base + A_STAGE + off, gb + (size_t)i * 32 * HID);
    }
}

__global__ __launch_bounds__(256, 2)
void mma_gemm_kernel(const __half* __restrict__ x,
                     const __half* __restrict__ w,
                     const float* __restrict__ lB,
                     float* __restrict__ out) {
    extern __shared__ __align__(16) char dsm[];
    const uint32_t tiles = smem_u32(dsm);

    const int tid  = threadIdx.x;
    const int wid  = tid >> 5;
    const int lane = tid & 31;
    const int wm   = (wid & 1) * 64;     // warp m offset
    const int wn   = (wid >> 1) * 32;    // warp n offset
    const int m0   = blockIdx.y * BM;
    const int n0   = blockIdx.x * BN;

    uint32_t aoff[4];
#pragma unroll
    for (int mt = 0; mt < 4; mt++)
        aoff[mt] = (uint32_t)(wm + mt * 16 + (lane & 15)) * ROWB + (lane >> 4) * 16;
    uint32_t boff[4];
#pragma unroll
    for (int nt = 0; nt < 4; nt++)
        boff[nt] = (uint32_t)(wn + nt * 8 + (lane & 7)) * ROWB + (lane >> 3) * 16;

    float c[4][4][4];
#pragma unroll
    for (int i = 0; i < 4; i++)
#pragma unroll
        for (int j = 0; j < 4; j++)
#pragma unroll
            for (int t = 0; t < 4; t++) c[i][j][t] = 0.f;

    // prologue: chunks 0, 1 into stages 0, 1
    load_chunk(tiles + 0 * STAGE_BYTES, x, w, m0, n0, 0 * BK, tid);
    CP_COMMIT();
    load_chunk(tiles + 1 * STAGE_BYTES, x, w, m0, n0, 1 * BK, tid);
    CP_COMMIT();

    uint32_t Bf[4][4];     // current k32-half B fragments
    uint32_t A0[4][4];     // A fragments, even k16 step
    uint32_t A1[4][4];     // A fragments, odd  k16 step

    for (int k = 0; k < NCHUNK; k++) {
        CP_WAIT1();            // chunk k resident
        __syncthreads();       // publish chunk k; chunk k-1 reads done

        const uint32_t sA = tiles + (k % STAGES) * STAGE_BYTES;
        const uint32_t sB = sA + A_STAGE;

        // ---- fill: B(h0), A(k0), A(k1) ----
#pragma unroll
        for (int nt = 0; nt < 4; nt++) ldsm4(Bf[nt], sB + boff[nt]);
#pragma unroll
        for (int mt = 0; mt < 4; mt++) ldsm4(A0[mt], sA + aoff[mt]);
#pragma unroll
        for (int mt = 0; mt < 4; mt++) ldsm4(A1[mt], sA + aoff[mt] + 32);

        // ---- MMA k0 (operands issued 8+ ldsm ago) ----
#pragma unroll
        for (int mt = 0; mt < 4; mt++)
#pragma unroll
            for (int nt = 0; nt < 4; nt++)
                mma_f16(c[mt][nt], A0[mt], Bf[nt][0], Bf[nt][1]);

        // ---- global prefetch of chunk k+2 in the MMA shadow ----
        if (k + 2 < NCHUNK)
            load_chunk(tiles + ((k + 2) % STAGES) * STAGE_BYTES,
                       x, w, m0, n0, (k + 2) * BK, tid);
        CP_COMMIT();           // one group per iter (empty at tail)

        // ---- A(k2) into A0 (WAR-safe: k0 MMAs already issued) ----
#pragma unroll
        for (int mt = 0; mt < 4; mt++) ldsm4(A0[mt], sA + aoff[mt] + 64);

        // ---- MMA k1 ----
#pragma unroll
        for (int mt = 0; mt < 4; mt++)
#pragma unroll
            for (int nt = 0; nt < 4; nt++)
                mma_f16(c[mt][nt], A1[mt], Bf[nt][2], Bf[nt][3]);

        // ---- B(h1) (WAR-safe after k1 MMAs) and A(k3) into A1 ----
#pragma unroll
        for (int nt = 0; nt < 4; nt++) ldsm4(Bf[nt], sB + boff[nt] + 64);
#pragma unroll
        for (int mt = 0; mt < 4; mt++) ldsm4(A1[mt], sA + aoff[mt] + 96);

        // ---- MMA k2 (A0 loaded 1 group ago; Bf fresh but 8 ldsm deep) ----
#pragma unroll
        for (int mt = 0; mt < 4; mt++)
#pragma unroll
            for (int nt = 0; nt < 4; nt++)
                mma_f16(c[mt][nt], A0[mt], Bf[nt][0], Bf[nt][1]);

        // ---- MMA k3 ----
#pragma unroll
        for (int mt = 0; mt < 4; mt++)
#pragma unroll
            for (int nt = 0; nt < 4; nt++)
                mma_f16(c[mt][nt], A1[mt], Bf[nt][2], Bf[nt][3]);
    }

    // ---- epilogue: add LoRA delta, write out ----
    const int rowg = lane >> 2;          // 0..7
    const int colg = (lane & 3) * 2;
#pragma unroll
    for (int mt = 0; mt < 4; mt++) {
#pragma unroll
        for (int hr = 0; hr < 2; hr++) {
            const int row = m0 + wm + mt * 16 + hr * 8 + rowg;
            const int e   = g_top1[row];
            const float4* zz = reinterpret_cast<const float4*>(g_zs + (size_t)row * RNK);
            const float4 z0 = zz[0], z1 = zz[1];
            const float* lbe = lB + (size_t)e * HID * RNK;
            float* orow = out + (size_t)row * HID;
#pragma unroll
            for (int nt = 0; nt < 4; nt++) {
                const int col = n0 + wn + nt * 8 + colg;
                const float4* bp =
                    reinterpret_cast<const float4*>(lbe + (size_t)col * RNK);
                const float4 b0 = bp[0], b1 = bp[1];
                const float4* bq =
                    reinterpret_cast<const float4*>(lbe + (size_t)(col + 1) * RNK);
                const float4 q0 = bq[0], q1 = bq[1];
                float d0 = z0.x * b0.x + z0.y * b0.y + z0.z * b0.z + z0.w * b0.w
                         + z1.x * b1.x + z1.y * b1.y + z1.z * b1.z + z1.w * b1.w;
                float d1 = z0.x * q0.x + z0.y * q0.y + z0.z * q0.z + z0.w * q0.w
                         + z1.x * q1.x + z1.y * q1.y + z1.z * q1.z + z1.w * q1.w;
                float2 res = make_float2(c[mt][nt][hr * 2 + 0] + d0,
                                         c[mt][nt][hr * 2 + 1] + d1);
                *reinterpret_cast<float2*>(orow + col) = res;
            }
        }
    }
}

// ---------------------------------------------------------------------------
extern "C" void kernel_launch(void* const* d_in, const int* in_sizes, int n_in,
                              void* d_out, int out_size) {
    const float* x    = (const float*)d_in[0];
    const float* W_up = (const float*)d_in[1];
    const float* gw   = (const float*)d_in[2];
    const float* bias = (const float*)d_in[3];
    const float* lA   = (const float*)d_in[4];
    const float* lBm  = (const float*)d_in[5];
    float* out        = (float*)d_out;

    const int N = in_sizes[0] / HID;   // 16384 tokens

    cudaFuncSetAttribute(mma_gemm_kernel,
                         cudaFuncAttributeMaxDynamicSharedMemorySize, DYN_SMEM);
    cudaFuncSetAttribute(mma_gemm_kernel,
                         cudaFuncAttributePreferredSharedMemoryCarveout, 100);

    __half* xh = nullptr;
    __half* wh = nullptr;
    cudaGetSymbolAddress((void**)&xh, g_xh);
    cudaGetSymbolAddress((void**)&wh, g_wh);

    // W pre-pass; x converted inside gate_z_kernel
    const int n8w = HID * HID / 8;
    cvt_f16_kernel<<<2048, 256>>>((const float4*)W_up, (uint4*)wh, n8w);

    gate_z_kernel<<<N, 128>>>(x, gw, bias, lA);

    dim3 grid(HID / BN, N / BM);       // (32, 128)
    mma_gemm_kernel<<<grid, 256, DYN_SMEM>>>(xh, wh, lBm, out);
}

// round 11
// speedup vs baseline: 2.7710x; 1.1167x over previous
#include <cuda_runtime.h>
#include <cuda_fp16.h>
#include <cstdint>

// ---------------- problem constants ----------------
#define HID   4096
#define NEXP  4
#define RNK   8
#define MAXN  16384

// ---------------- GEMM tiling (fp16 operands) ----------------
#define BM 128
#define BN 128
#define BK 64                         // fp16 elements per K-chunk (128 bytes)
#define NCHUNK (HID / BK)             // 64
#define ROWB   144                    // 64 halves (128B) + 16B pad
#define A_STAGE (BM * ROWB)           // 18432
#define STAGE_BYTES (2 * A_STAGE)     // 36864
#define STAGES 3
#define DYN_SMEM (STAGES * STAGE_BYTES)   // 110592
#define NROUND ((NCHUNK + 2) / 3)     // 22

// scratch (allocation-free rule: __device__ globals live in bss)
__device__ float   g_zs[MAXN * RNK];
__device__ int     g_top1[MAXN];
__device__ __half  g_xh[(size_t)MAXN * HID];   // fp16 x   (128 MB)
__device__ __half  g_wh[(size_t)HID * HID];    // fp16 W   (32 MB)

// ---------------- PTX helpers ----------------
__device__ __forceinline__ uint32_t smem_u32(const void* p) {
    uint32_t a;
    asm("{ .reg .u64 t; cvta.to.shared.u64 t, %1; cvt.u32.u64 %0, t; }"
        : "=r"(a) : "l"(p));
    return a;
}
__device__ __forceinline__ void cp_async16(uint32_t dst, const void* src) {
    asm volatile("cp.async.cg.shared.global [%0], [%1], 16;"
                 :: "r"(dst), "l"(src) : "memory");
}
#define MBAR_INIT(a, c) \
    asm volatile("mbarrier.init.shared.b64 [%0], %1;" :: "r"(a), "r"(c) : "memory")
#define MBAR_ARRIVE(a) \
    asm volatile("mbarrier.arrive.shared.b64 _, [%0];" :: "r"(a) : "memory")
#define CPA_MBAR_ARRIVE(a) \
    asm volatile("cp.async.mbarrier.arrive.noinc.shared.b64 [%0];" :: "r"(a) : "memory")

__device__ __forceinline__ void mbar_wait(uint32_t addr, uint32_t parity) {
    asm volatile(
        "{\n\t.reg .pred P;\n\t"
        "W_%=:\n\t"
        "mbarrier.try_wait.parity.acquire.cta.shared::cta.b64 P, [%0], %1, 0x989680;\n\t"
        "@P bra.uni D_%=;\n\t"
        "bra.uni W_%=;\n\t"
        "D_%=:\n\t}"
        :: "r"(addr), "r"(parity) : "memory");
}

__device__ __forceinline__ void ldsm4(uint32_t* d, uint32_t addr) {
    asm volatile("ldmatrix.sync.aligned.m8n8.x4.shared.b16 {%0,%1,%2,%3}, [%4];"
                 : "=r"(d[0]), "=r"(d[1]), "=r"(d[2]), "=r"(d[3]) : "r"(addr));
}
__device__ __forceinline__ uint32_t pack_h2(float lo, float hi) {
    uint32_t r;
    asm("cvt.rn.f16x2.f32 %0, %1, %2;" : "=r"(r) : "f"(hi), "f"(lo));
    return r;
}
__device__ __forceinline__ void mma_f16(float* c, const uint32_t* a,
                                        uint32_t b0, uint32_t b1) {
    asm volatile(
        "mma.sync.aligned.m16n8k16.row.col.f32.f16.f16.f32 "
        "{%0,%1,%2,%3},{%4,%5,%6,%7},{%8,%9},{%0,%1,%2,%3};"
        : "+f"(c[0]), "+f"(c[1]), "+f"(c[2]), "+f"(c[3])
        : "r"(a[0]), "r"(a[1]), "r"(a[2]), "r"(a[3]), "r"(b0), "r"(b1));
}

// ---------------------------------------------------------------------------
// Kernel P: one-shot f32 -> fp16 pre-pass for W. x is converted in gate_z.
// ---------------------------------------------------------------------------
__global__ void cvt_f16_kernel(const float4* __restrict__ src,
                               uint4* __restrict__ dst, int n8) {
    for (int i = blockIdx.x * blockDim.x + threadIdx.x; i < n8;
         i += gridDim.x * blockDim.x) {
        float4 v0 = src[2 * i], v1 = src[2 * i + 1];
        uint4 o;
        o.x = pack_h2(v0.x, v0.y);
        o.y = pack_h2(v0.z, v0.w);
        o.z = pack_h2(v1.x, v1.y);
        o.w = pack_h2(v1.z, v1.w);
        dst[i] = o;
    }
}

// ---------------------------------------------------------------------------
// Kernel A: gating + LoRA z, x row cached in smem (single global read of x)
// ---------------------------------------------------------------------------
__global__ void gate_z_kernel(const float* __restrict__ x,
                              const float* __restrict__ gw,
                              const float* __restrict__ bias,
                              const float* __restrict__ lA) {
    const int n    = blockIdx.x;
    const int tid  = threadIdx.x;
    const int wid  = tid >> 5;
    const int lane = tid & 31;

    __shared__ float sx[HID];            // 16 KB x-row cache
    __shared__ float sred[4][RNK];
    __shared__ int   s_e;
    float4* sx4 = reinterpret_cast<float4*>(sx);

    const float4* xr = reinterpret_cast<const float4*>(x + (size_t)n * HID);
    uint2* xh2 = reinterpret_cast<uint2*>(g_xh + (size_t)n * HID);

    float a[NEXP] = {0.f, 0.f, 0.f, 0.f};
    const float4* gw4 = reinterpret_cast<const float4*>(gw);
    for (int h = tid; h < HID / 4; h += 128) {
        float4 xv = xr[h];
        sx4[h] = xv;                      // cache for phase 2
        uint2 o;                          // fused fp16 conversion
        o.x = pack_h2(xv.x, xv.y);
        o.y = pack_h2(xv.z, xv.w);
        xh2[h] = o;
#pragma unroll
        for (int e = 0; e < NEXP; e++) {
            float4 g = gw4[e * (HID / 4) + h];
            a[e] += xv.x * g.x + xv.y * g.y + xv.z * g.z + xv.w * g.w;
        }
    }
#pragma unroll
    for (int e = 0; e < NEXP; e++)
#pragma unroll
        for (int off = 16; off > 0; off >>= 1)
            a[e] += __shfl_xor_sync(0xffffffffu, a[e], off);
    if (lane == 0)
#pragma unroll
        for (int e = 0; e < NEXP; e++) sred[wid][e] = a[e];
    __syncthreads();
    if (tid == 0) {
        float best = -3.4e38f; int be = 0;
#pragma unroll
        for (int e = 0; e < NEXP; e++) {
            float v = sred[0][e] + sred[1][e] + sred[2][e] + sred[3][e] + bias[e];
            if (v > best) { best = v; be = e; }
        }
        s_e = be;
        g_top1[n] = be;
    }
    __syncthreads();

    const int e = s_e;
    const float4* A4 = reinterpret_cast<const float4*>(lA + (size_t)e * RNK * HID);
    float z[RNK];
#pragma unroll
    for (int r = 0; r < RNK; r++) z[r] = 0.f;
    for (int h = tid; h < HID / 4; h += 128) {
        float4 xv = sx4[h];               // from smem, no global re-read
#pragma unroll
        for (int r = 0; r < RNK; r++) {
            float4 g = A4[r * (HID / 4) + h];
            z[r] += xv.x * g.x + xv.y * g.y + xv.z * g.z + xv.w * g.w;
        }
    }
#pragma unroll
    for (int r = 0; r < RNK; r++)
#pragma unroll
        for (int off = 16; off > 0; off >>= 1)
            z[r] += __shfl_xor_sync(0xffffffffu, z[r], off);
    __syncthreads();
    if (lane == 0)
#pragma unroll
        for (int r = 0; r < RNK; r++) sred[wid][r] = z[r];
    __syncthreads();
    if (tid < RNK)
        g_zs[(size_t)n * RNK + tid] =
            sred[0][tid] + sred[1][tid] + sred[2][tid] + sred[3][tid];
}

// ---------------------------------------------------------------------------
// Kernel B: fp16 GEMM, mbarrier producer/consumer ring (no __syncthreads in
// the mainloop). full[s]: 256 cp.async-completion arrivals. empty[s]: 256
// consumer arrivals placed right after the last ldmatrix of that stage.
// Warps decouple across chunk boundaries; skew absorbed by 3-stage depth.
// ---------------------------------------------------------------------------
__device__ __forceinline__ void load_chunk(uint32_t base,
                                           const __half* __restrict__ x,
                                           const __half* __restrict__ w,
                                           int m0, int n0, int k0, int tid) {
    const int seg = tid & 7;
    const int r0  = tid >> 3;
    const __half* ga = x + (size_t)(m0 + r0) * HID + k0 + seg * 8;
    const __half* gb = w + (size_t)(n0 + r0) * HID + k0 + seg * 8;
#pragma unroll
    for (int i = 0; i < 4; i++) {
        const uint32_t off = (uint32_t)(r0 + i * 32) * ROWB + seg * 16;
        cp_async16(base + off,           ga + (size_t)i * 32 * HID);
        cp_async16(base + A_STAGE + off, gb + (size_t)i * 32 * HID);
    }
}

__global__ __launch_bounds__(256, 2)
void mma_gemm_kernel(const __half* __restrict__ x,
                     const __half* __restrict__ w,
                     const float* __restrict__ lB,
                     float* __restrict__ out) {
    extern __shared__ __align__(16) char dsm[];
    const uint32_t tiles = smem_u32(dsm);

    __shared__ __align__(8) unsigned long long s_bar[2 * STAGES];
    const uint32_t bfull  = smem_u32(s_bar);            // full[s]  at +8s
    const uint32_t bempty = bfull + 8 * STAGES;         // empty[s] at +8s

    const int tid  = threadIdx.x;
    const int wid  = tid >> 5;
    const int lane = tid & 31;
    const int wm   = (wid & 1) * 64;
    const int wn   = (wid >> 1) * 32;
    const int m0   = blockIdx.y * BM;
    const int n0   = blockIdx.x * BN;

    uint32_t aoff[4];
#pragma unroll
    for (int mt = 0; mt < 4; mt++)
        aoff[mt] = (uint32_t)(wm + mt * 16 + (lane & 15)) * ROWB + (lane >> 4) * 16;
    uint32_t boff[4];
#pragma unroll
    for (int nt = 0; nt < 4; nt++)
        boff[nt] = (uint32_t)(wn + nt * 8 + (lane & 7)) * ROWB + (lane >> 3) * 16;

    float c[4][4][4];
#pragma unroll
    for (int i = 0; i < 4; i++)
#pragma unroll
        for (int j = 0; j < 4; j++)
#pragma unroll
            for (int t = 0; t < 4; t++) c[i][j][t] = 0.f;

    if (tid == 0) {
#pragma unroll
        for (int s = 0; s < STAGES; s++) {
            MBAR_INIT(bfull  + 8 * s, 256);
            MBAR_INIT(bempty + 8 * s, 256);
        }
    }
    __syncthreads();

    // prologue: produce chunks 0 (stage0) and 1 (stage1)
    load_chunk(tiles + 0 * STAGE_BYTES, x, w, m0, n0, 0 * BK, tid);
    CPA_MBAR_ARRIVE(bfull + 0);
    load_chunk(tiles + 1 * STAGE_BYTES, x, w, m0, n0, 1 * BK, tid);
    CPA_MBAR_ARRIVE(bfull + 8);

    uint32_t Bf[4][4], A0[4][4], A1[4][4];

    // CONSUME chunk k from stage S (parity PF); then PRODUCE chunk k+2 into
    // stage S2 (empty parity PE, waited only when DOWAIT).
#define SLOT(S, S2, PF, PE, DOWAIT, KK)                                        \
    if ((KK) < NCHUNK) {                                                       \
        mbar_wait(bfull + 8 * (S), (PF));                                      \
        const uint32_t sA = tiles + (S) * STAGE_BYTES;                         \
        const uint32_t sB = sA + A_STAGE;                                      \
        _Pragma("unroll")                                                      \
        for (int nt = 0; nt < 4; nt++) ldsm4(Bf[nt], sB + boff[nt]);           \
        _Pragma("unroll")                                                      \
        for (int mt = 0; mt < 4; mt++) ldsm4(A0[mt], sA + aoff[mt]);           \
        _Pragma("unroll")                                                      \
        for (int mt = 0; mt < 4; mt++) ldsm4(A1[mt], sA + aoff[mt] + 32);      \
        _Pragma("unroll")                                                      \
        for (int mt = 0; mt < 4; mt++)                                         \
            _Pragma("unroll")                                                  \
            for (int nt = 0; nt < 4; nt++)                                     \
                mma_f16(c[mt][nt], A0[mt], Bf[nt][0], Bf[nt][1]);              \
        _Pragma("unroll")                                                      \
        for (int mt = 0; mt < 4; mt++) ldsm4(A0[mt], sA + aoff[mt] + 64);      \
        _Pragma("unroll")                                                      \
        for (int mt = 0; mt < 4; mt++)                                         \
            _Pragma("unroll")                                                  \
            for (int nt = 0; nt < 4; nt++)                                     \
                mma_f16(c[mt][nt], A1[mt], Bf[nt][2], Bf[nt][3]);              \
        _Pragma("unroll")                                                      \
        for (int nt = 0; nt < 4; nt++) ldsm4(Bf[nt], sB + boff[nt] + 64);      \
        _Pragma("unroll")                                                      \
        for (int mt = 0; mt < 4; mt++) ldsm4(A1[mt], sA + aoff[mt] + 96);      \
        MBAR_ARRIVE(bempty + 8 * (S));  /* all reads of stage S done */        \
        if ((KK) + 2 < NCHUNK) {                                               \
            if (DOWAIT) mbar_wait(bempty + 8 * (S2), (PE));                    \
            load_chunk(tiles + (S2) * STAGE_BYTES, x, w, m0, n0,               \
                       ((KK) + 2) * BK, tid);                                  \
            CPA_MBAR_ARRIVE(bfull + 8 * (S2));                                 \
        }                                                                      \
        _Pragma("unroll")                                                      \
        for (int mt = 0; mt < 4; mt++)                                         \
            _Pragma("unroll")                                                  \
            for (int nt = 0; nt < 4; nt++)                                     \
                mma_f16(c[mt][nt], A0[mt], Bf[nt][0], Bf[nt][1]);              \
        _Pragma("unroll")                                                      \
        for (int mt = 0; mt < 4; mt++)                                         \
            _Pragma("unroll")                                                  \
            for (int nt = 0; nt < 4; nt++)                                     \
                mma_f16(c[mt][nt], A1[mt], Bf[nt][2], Bf[nt][3]);              \
    }

    for (int j = 0; j < NROUND; j++) {
        const uint32_t pf = (uint32_t)(j & 1);
        const uint32_t pm = (uint32_t)((j - 1) & 1);
        // slot0: k=3j, stage0 -> produce 3j+2 into stage2 (skip wait at j=0)
        SLOT(0, 2, pf, pm, (j >= 1), 3 * j + 0);
        // slot1: k=3j+1, stage1 -> produce 3j+3 into stage0 (wait chunk 3j)
        SLOT(1, 0, pf, pf, true, 3 * j + 1);
        // slot2: k=3j+2, stage2 -> produce 3j+4 into stage1 (wait chunk 3j+1)
        SLOT(2, 1, pf, pf, true, 3 * j + 2);
    }
#undef SLOT

    // ---- epilogue: add LoRA delta, write out ----
    const int rowg = lane >> 2;
    const int colg = (lane & 3) * 2;
#pragma unroll
    for (int mt = 0; mt < 4; mt++) {
#pragma unroll
        for (int hr = 0; hr < 2; hr++) {
            const int row = m0 + wm + mt * 16 + hr * 8 + rowg;
            const int e   = g_top1[row];
            const float4* zz = reinterpret_cast<const float4*>(g_zs + (size_t)row * RNK);
            const float4 z0 = zz[0], z1 = zz[1];
            const float* lbe = lB + (size_t)e * HID * RNK;
            float* orow = out + (size_t)row * HID;
#pragma unroll
            for (int nt = 0; nt < 4; nt++) {
                const int col = n0 + wn + nt * 8 + colg;
                const float4* bp =
                    reinterpret_cast<const float4*>(lbe + (size_t)col * RNK);
                const float4 b0 = bp[0], b1 = bp[1];
                const float4* bq =
                    reinterpret_cast<const float4*>(lbe + (size_t)(col + 1) * RNK);
                const float4 q0 = bq[0], q1 = bq[1];
                float d0 = z0.x * b0.x + z0.y * b0.y + z0.z * b0.z + z0.w * b0.w
                         + z1.x * b1.x + z1.y * b1.y + z1.z * b1.z + z1.w * b1.w;
                float d1 = z0.x * q0.x + z0.y * q0.y + z0.z * q0.z + z0.w * q0.w
                         + z1.x * q1.x + z1.y * q1.y + z1.z * q1.z + z1.w * q1.w;
                float2 res = make_float2(c[mt][nt][hr * 2 + 0] + d0,
                                         c[mt][nt][hr * 2 + 1] + d1);
                *reinterpret_cast<float2*>(orow + col) = res;
            }
        }
    }
}

// ---------------------------------------------------------------------------
extern "C" void kernel_launch(void* const* d_in, const int* in_sizes, int n_in,
                              void* d_out, int out_size) {
    const float* x    = (const float*)d_in[0];
    const float* W_up = (const float*)d_in[1];
    const float* gw   = (const float*)d_in[2];
    const float* bias = (const float*)d_in[3];
    const float* lA   = (const float*)d_in[4];
    const float* lBm  = (const float*)d_in[5];
    float* out        = (float*)d_out;

    const int N = in_sizes[0] / HID;   // 16384 tokens

    cudaFuncSetAttribute(mma_gemm_kernel,
                         cudaFuncAttributeMaxDynamicSharedMemorySize, DYN_SMEM);
    cudaFuncSetAttribute(mma_gemm_kernel,
                         cudaFuncAttributePreferredSharedMemoryCarveout, 100);

    __half* xh = nullptr;
    __half* wh = nullptr;
    cudaGetSymbolAddress((void**)&xh, g_xh);
    cudaGetSymbolAddress((void**)&wh, g_wh);

    const int n8w = HID * HID / 8;
    cvt_f16_kernel<<<2048, 256>>>((const float4*)W_up, (uint4*)wh, n8w);

    gate_z_kernel<<<N, 128>>>(x, gw, bias, lA);

    dim3 grid(HID / BN, N / BM);       // (32, 128)
    mma_gemm_kernel<<<grid, 256, DYN_SMEM>>>(xh, wh, lBm, out);
}

// round 12
// speedup vs baseline: 2.7935x; 1.0081x over previous
#include <cuda_runtime.h>
#include <cuda_fp16.h>
#include <cstdint>

// ---------------- problem constants ----------------
#define HID   4096
#define NEXP  4
#define RNK   8
#define MAXN  16384

// ---------------- GEMM tiling (fp16 operands) ----------------
#define BM 128
#define BN 256
#define BK 64                         // fp16 elements per K-chunk (128 bytes)
#define NCHUNK (HID / BK)             // 64
#define ROWB   144                    // 64 halves (128B) + 16B pad
#define A_ST   (BM * ROWB)            // 18432
#define B_ST   (BN * ROWB)            // 36864
#define STAGE_BYTES (A_ST + B_ST)     // 55296
#define STAGES 3
#define DYN_SMEM (STAGES * STAGE_BYTES)   // 165888
#define NROUND ((NCHUNK + 2) / 3)     // 22

// scratch (allocation-free rule: __device__ globals live in bss)
__device__ float   g_zs[MAXN * RNK];
__device__ int     g_top1[MAXN];
__device__ __half  g_xh[(size_t)MAXN * HID];   // fp16 x   (128 MB)
__device__ __half  g_wh[(size_t)HID * HID];    // fp16 W   (32 MB)

// ---------------- PTX helpers ----------------
__device__ __forceinline__ uint32_t smem_u32(const void* p) {
    uint32_t a;
    asm("{ .reg .u64 t; cvta.to.shared.u64 t, %1; cvt.u32.u64 %0, t; }"
        : "=r"(a) : "l"(p));
    return a;
}
__device__ __forceinline__ void cp_async16(uint32_t dst, const void* src) {
    asm volatile("cp.async.cg.shared.global [%0], [%1], 16;"
                 :: "r"(dst), "l"(src) : "memory");
}
#define MBAR_INIT(a, c) \
    asm volatile("mbarrier.init.shared.b64 [%0], %1;" :: "r"(a), "r"(c) : "memory")
#define MBAR_ARRIVE(a) \
    asm volatile("mbarrier.arrive.shared.b64 _, [%0];" :: "r"(a) : "memory")
#define CPA_MBAR_ARRIVE(a) \
    asm volatile("cp.async.mbarrier.arrive.noinc.shared.b64 [%0];" :: "r"(a) : "memory")

__device__ __forceinline__ void mbar_wait(uint32_t addr, uint32_t parity) {
    asm volatile(
        "{\n\t.reg .pred P;\n\t"
        "W_%=:\n\t"
        "mbarrier.try_wait.parity.acquire.cta.shared::cta.b64 P, [%0], %1, 0x989680;\n\t"
        "@P bra.uni D_%=;\n\t"
        "bra.uni W_%=;\n\t"
        "D_%=:\n\t}"
        :: "r"(addr), "r"(parity) : "memory");
}

__device__ __forceinline__ void ldsm4(uint32_t* d, uint32_t addr) {
    asm volatile("ldmatrix.sync.aligned.m8n8.x4.shared.b16 {%0,%1,%2,%3}, [%4];"
                 : "=r"(d[0]), "=r"(d[1]), "=r"(d[2]), "=r"(d[3]) : "r"(addr));
}
__device__ __forceinline__ uint32_t pack_h2(float lo, float hi) {
    uint32_t r;
    asm("cvt.rn.f16x2.f32 %0, %1, %2;" : "=r"(r) : "f"(hi), "f"(lo));
    return r;
}
__device__ __forceinline__ void mma_f16(float* c, const uint32_t* a,
                                        uint32_t b0, uint32_t b1) {
    asm volatile(
        "mma.sync.aligned.m16n8k16.row.col.f32.f16.f16.f32 "
        "{%0,%1,%2,%3},{%4,%5,%6,%7},{%8,%9},{%0,%1,%2,%3};"
        : "+f"(c[0]), "+f"(c[1]), "+f"(c[2]), "+f"(c[3])
        : "r"(a[0]), "r"(a[1]), "r"(a[2]), "r"(a[3]), "r"(b0), "r"(b1));
}

// ---------------------------------------------------------------------------
// Kernel P: one-shot f32 -> fp16 pre-pass for W. x is converted in gate_z.
// ---------------------------------------------------------------------------
__global__ void cvt_f16_kernel(const float4* __restrict__ src,
                               uint4* __restrict__ dst, int n8) {
    for (int i = blockIdx.x * blockDim.x + threadIdx.x; i < n8;
         i += gridDim.x * blockDim.x) {
        float4 v0 = src[2 * i], v1 = src[2 * i + 1];
        uint4 o;
        o.x = pack_h2(v0.x, v0.y);
        o.y = pack_h2(v0.z, v0.w);
        o.z = pack_h2(v1.x, v1.y);
        o.w = pack_h2(v1.z, v1.w);
        dst[i] = o;
    }
}

// ---------------------------------------------------------------------------
// Kernel A: gating + LoRA z, x row cached in smem + fused f16(x) conversion
// ---------------------------------------------------------------------------
__global__ void gate_z_kernel(const float* __restrict__ x,
                              const float* __restrict__ gw,
                              const float* __restrict__ bias,
                              const float* __restrict__ lA) {
    const int n    = blockIdx.x;
    const int tid  = threadIdx.x;
    const int wid  = tid >> 5;
    const int lane = tid & 31;

    __shared__ float sx[HID];
    __shared__ float sred[4][RNK];
    __shared__ int   s_e;
    float4* sx4 = reinterpret_cast<float4*>(sx);

    const float4* xr = reinterpret_cast<const float4*>(x + (size_t)n * HID);
    uint2* xh2 = reinterpret_cast<uint2*>(g_xh + (size_t)n * HID);

    float a[NEXP] = {0.f, 0.f, 0.f, 0.f};
    const float4* gw4 = reinterpret_cast<const float4*>(gw);
    for (int h = tid; h < HID / 4; h += 128) {
        float4 xv = xr[h];
        sx4[h] = xv;
        uint2 o;
        o.x = pack_h2(xv.x, xv.y);
        o.y = pack_h2(xv.z, xv.w);
        xh2[h] = o;
#pragma unroll
        for (int e = 0; e < NEXP; e++) {
            float4 g = gw4[e * (HID / 4) + h];
            a[e] += xv.x * g.x + xv.y * g.y + xv.z * g.z + xv.w * g.w;
        }
    }
#pragma unroll
    for (int e = 0; e < NEXP; e++)
#pragma unroll
        for (int off = 16; off > 0; off >>= 1)
            a[e] += __shfl_xor_sync(0xffffffffu, a[e], off);
    if (lane == 0)
#pragma unroll
        for (int e = 0; e < NEXP; e++) sred[wid][e] = a[e];
    __syncthreads();
    if (tid == 0) {
        float best = -3.4e38f; int be = 0;
#pragma unroll
        for (int e = 0; e < NEXP; e++) {
            float v = sred[0][e] + sred[1][e] + sred[2][e] + sred[3][e] + bias[e];
            if (v > best) { best = v; be = e; }
        }
        s_e = be;
        g_top1[n] = be;
    }
    __syncthreads();

    const int e = s_e;
    const float4* A4 = reinterpret_cast<const float4*>(lA + (size_t)e * RNK * HID);
    float z[RNK];
#pragma unroll
    for (int r = 0; r < RNK; r++) z[r] = 0.f;
    for (int h = tid; h < HID / 4; h += 128) {
        float4 xv = sx4[h];
#pragma unroll
        for (int r = 0; r < RNK; r++) {
            float4 g = A4[r * (HID / 4) + h];
            z[r] += xv.x * g.x + xv.y * g.y + xv.z * g.z + xv.w * g.w;
        }
    }
#pragma unroll
    for (int r = 0; r < RNK; r++)
#pragma unroll
        for (int off = 16; off > 0; off >>= 1)
            z[r] += __shfl_xor_sync(0xffffffffu, z[r], off);
    __syncthreads();
    if (lane == 0)
#pragma unroll
        for (int r = 0; r < RNK; r++) sred[wid][r] = z[r];
    __syncthreads();
    if (tid < RNK)
        g_zs[(size_t)n * RNK + tid] =
            sred[0][tid] + sred[1][tid] + sred[2][tid] + sred[3][tid];
}

// ---------------------------------------------------------------------------
// Kernel B: fp16 GEMM. CTA 128x256x64, warp tile 64x64 (warp grid 2m x 4n),
// 256 threads, 1 CTA/SM, 3-stage mbarrier producer/consumer ring.
// Smem traffic: 0.71 B/FLOP (was 1.22) -> tensor pipe becomes the floor.
// ---------------------------------------------------------------------------
__device__ __forceinline__ void load_chunk(uint32_t base,
                                           const __half* __restrict__ x,
                                           const __half* __restrict__ w,
                                           int m0, int n0, int k0, int tid) {
    const int seg = tid & 7;
    const int r0  = tid >> 3;            // 0..31
    const __half* ga = x + (size_t)(m0 + r0) * HID + k0 + seg * 8;
    const __half* gb = w + (size_t)(n0 + r0) * HID + k0 + seg * 8;
#pragma unroll
    for (int i = 0; i < 4; i++) {        // A: 128 rows
        const uint32_t off = (uint32_t)(r0 + i * 32) * ROWB + seg * 16;
        cp_async16(base + off, ga + (size_t)i * 32 * HID);
    }
#pragma unroll
    for (int i = 0; i < 8; i++) {        // B: 256 rows
        const uint32_t off = (uint32_t)(r0 + i * 32) * ROWB + seg * 16;
        cp_async16(base + A_ST + off, gb + (size_t)i * 32 * HID);
    }
}

__global__ __launch_bounds__(256, 1)
void mma_gemm_kernel(const __half* __restrict__ x,
                     const __half* __restrict__ w,
                     const float* __restrict__ lB,
                     float* __restrict__ out) {
    extern __shared__ __align__(16) char dsm[];
    const uint32_t tiles = smem_u32(dsm);

    __shared__ __align__(8) unsigned long long s_bar[2 * STAGES];
    const uint32_t bfull  = smem_u32(s_bar);
    const uint32_t bempty = bfull + 8 * STAGES;

    const int tid  = threadIdx.x;
    const int wid  = tid >> 5;
    const int lane = tid & 31;
    const int wm   = (wid & 1) * 64;     // warp m offset (2 warps in m)
    const int wn   = (wid >> 1) * 64;    // warp n offset (4 warps in n)
    const int m0   = blockIdx.y * BM;
    const int n0   = blockIdx.x * BN;

    uint32_t aoff[4];
#pragma unroll
    for (int mt = 0; mt < 4; mt++)
        aoff[mt] = (uint32_t)(wm + mt * 16 + (lane & 15)) * ROWB + (lane >> 4) * 16;
    uint32_t boff[8];
#pragma unroll
    for (int nt = 0; nt < 8; nt++)
        boff[nt] = (uint32_t)(A_ST + (wn + nt * 8 + (lane & 7)) * ROWB) + (lane >> 3) * 16;

    float c[4][8][4];
#pragma unroll
    for (int i = 0; i < 4; i++)
#pragma unroll
        for (int j = 0; j < 8; j++)
#pragma unroll
            for (int t = 0; t < 4; t++) c[i][j][t] = 0.f;

    if (tid == 0) {
#pragma unroll
        for (int s = 0; s < STAGES; s++) {
            MBAR_INIT(bfull  + 8 * s, 256);
            MBAR_INIT(bempty + 8 * s, 256);
        }
    }
    __syncthreads();

    // prologue: produce chunks 0 (stage0) and 1 (stage1)
    load_chunk(tiles + 0 * STAGE_BYTES, x, w, m0, n0, 0 * BK, tid);
    CPA_MBAR_ARRIVE(bfull + 0);
    load_chunk(tiles + 1 * STAGE_BYTES, x, w, m0, n0, 1 * BK, tid);
    CPA_MBAR_ARRIVE(bfull + 8);

    uint32_t Bf[8][4], A0[4][4], A1[4][4];

#define SLOT(S, S2, PF, PE, DOWAIT, KK)                                        \
    if ((KK) < NCHUNK) {                                                       \
        mbar_wait(bfull + 8 * (S), (PF));                                      \
        const uint32_t sbase = tiles + (S) * STAGE_BYTES;                      \
        _Pragma("unroll")                                                      \
        for (int nt = 0; nt < 8; nt++) ldsm4(Bf[nt], sbase + boff[nt]);        \
        _Pragma("unroll")                                                      \
        for (int mt = 0; mt < 4; mt++) ldsm4(A0[mt], sbase + aoff[mt]);        \
        _Pragma("unroll")                                                      \
        for (int mt = 0; mt < 4; mt++) ldsm4(A1[mt], sbase + aoff[mt] + 32);   \
        _Pragma("unroll")                                                      \
        for (int mt = 0; mt < 4; mt++)                                         \
            _Pragma("unroll")                                                  \
            for (int nt = 0; nt < 8; nt++)                                     \
                mma_f16(c[mt][nt], A0[mt], Bf[nt][0], Bf[nt][1]);              \
        if ((KK) + 2 < NCHUNK) {                                               \
            if (DOWAIT) mbar_wait(bempty + 8 * (S2), (PE));                    \
            load_chunk(tiles + (S2) * STAGE_BYTES, x, w, m0, n0,               \
                       ((KK) + 2) * BK, tid);                                  \
            CPA_MBAR_ARRIVE(bfull + 8 * (S2));                                 \
        }                                                                      \
        _Pragma("unroll")                                                      \
        for (int mt = 0; mt < 4; mt++) ldsm4(A0[mt], sbase + aoff[mt] + 64);   \
        _Pragma("unroll")                                                      \
        for (int mt = 0; mt < 4; mt++)                                         \
            _Pragma("unroll")                                                  \
            for (int nt = 0; nt < 8; nt++)                                     \
                mma_f16(c[mt][nt], A1[mt], Bf[nt][2], Bf[nt][3]);              \
        _Pragma("unroll")                                                      \
        for (int nt = 0; nt < 8; nt++) ldsm4(Bf[nt], sbase + boff[nt] + 64);   \
        _Pragma("unroll")                                                      \
        for (int mt = 0; mt < 4; mt++) ldsm4(A1[mt], sbase + aoff[mt] + 96);   \
        _Pragma("unroll")                                                      \
        for (int mt = 0; mt < 4; mt++)                                         \
            _Pragma("unroll")                                                  \
            for (int nt = 0; nt < 8; nt++)                                     \
                mma_f16(c[mt][nt], A0[mt], Bf[nt][0], Bf[nt][1]);              \
        MBAR_ARRIVE(bempty + 8 * (S));                                         \
        _Pragma("unroll")                                                      \
        for (int mt = 0; mt < 4; mt++)                                         \
            _Pragma("unroll")                                                  \
            for (int nt = 0; nt < 8; nt++)                                     \
                mma_f16(c[mt][nt], A1[mt], Bf[nt][2], Bf[nt][3]);              \
    }

    for (int j = 0; j < NROUND; j++) {
        const uint32_t pf = (uint32_t)(j & 1);
        const uint32_t pm = (uint32_t)((j - 1) & 1);
        SLOT(0, 2, pf, pm, (j >= 1), 3 * j + 0);
        SLOT(1, 0, pf, pf, true,     3 * j + 1);
        SLOT(2, 1, pf, pf, true,     3 * j + 2);
    }
#undef SLOT

    // ---- epilogue: add LoRA delta, write out ----
    const int rowg = lane >> 2;
    const int colg = (lane & 3) * 2;
#pragma unroll
    for (int mt = 0; mt < 4; mt++) {
#pragma unroll
        for (int hr = 0; hr < 2; hr++) {
            const int row = m0 + wm + mt * 16 + hr * 8 + rowg;
            const int e   = g_top1[row];
            const float4* zz = reinterpret_cast<const float4*>(g_zs + (size_t)row * RNK);
            const float4 z0 = zz[0], z1 = zz[1];
            const float* lbe = lB + (size_t)e * HID * RNK;
            float* orow = out + (size_t)row * HID;
#pragma unroll
            for (int nt = 0; nt < 8; nt++) {
                const int col = n0 + wn + nt * 8 + colg;
                const float4* bp =
                    reinterpret_cast<const float4*>(lbe + (size_t)col * RNK);
                const float4 b0 = bp[0], b1 = bp[1];
                const float4* bq =
                    reinterpret_cast<const float4*>(lbe + (size_t)(col + 1) * RNK);
                const float4 q0 = bq[0], q1 = bq[1];
                float d0 = z0.x * b0.x + z0.y * b0.y + z0.z * b0.z + z0.w * b0.w
                         + z1.x * b1.x + z1.y * b1.y + z1.z * b1.z + z1.w * b1.w;
                float d1 = z0.x * q0.x + z0.y * q0.y + z0.z * q0.z + z0.w * q0.w
                         + z1.x * q1.x + z1.y * q1.y + z1.z * q1.z + z1.w * q1.w;
                float2 res = make_float2(c[mt][nt][hr * 2 + 0] + d0,
                                         c[mt][nt][hr * 2 + 1] + d1);
                *reinterpret_cast<float2*>(orow + col) = res;
            }
        }
    }
}

// ---------------------------------------------------------------------------
extern "C" void kernel_launch(void* const* d_in, const int* in_sizes, int n_in,
                              void* d_out, int out_size) {
    const float* x    = (const float*)d_in[0];
    const float* W_up = (const float*)d_in[1];
    const float* gw   = (const float*)d_in[2];
    const float* bias = (const float*)d_in[3];
    const float* lA   = (const float*)d_in[4];
    const float* lBm  = (const float*)d_in[5];
    float* out        = (float*)d_out;

    const int N = in_sizes[0] / HID;   // 16384 tokens

    cudaFuncSetAttribute(mma_gemm_kernel,
                         cudaFuncAttributeMaxDynamicSharedMemorySize, DYN_SMEM);
    cudaFuncSetAttribute(mma_gemm_kernel,
                         cudaFuncAttributePreferredSharedMemoryCarveout, 100);

    __half* xh = nullptr;
    __half* wh = nullptr;
    cudaGetSymbolAddress((void**)&xh, g_xh);
    cudaGetSymbolAddress((void**)&wh, g_wh);

    const int n8w = HID * HID / 8;
    cvt_f16_kernel<<<2048, 256>>>((const float4*)W_up, (uint4*)wh, n8w);

    gate_z_kernel<<<N, 128>>>(x, gw, bias, lA);

    dim3 grid(HID / BN, N / BM);       // (16, 128)
    mma_gemm_kernel<<<grid, 256, DYN_SMEM>>>(xh, wh, lBm, out);
}